// round 12
// baseline (speedup 1.0000x reference)
#include <cuda_runtime.h>
#include <cuda_bf16.h>

// ---------------- problem constants ----------------
constexpr int kNH = 6;
constexpr int kD  = 768;
constexpr int kHD = 128;
constexpr int kB  = 2;
constexpr int kT  = 2048;
constexpr int kBT = kB * kT;          // 4096
constexpr int kC  = 128;              // chunk size for Q reconstruction
constexpr int kNC = kT / kC;          // 16 chunks per sequence
constexpr float kEPS = 1e-6f;

constexpr int PITCH = 132;
constexpr int GP    = 132;

typedef unsigned long long ull;

// ---------------- device scratch ----------------
__device__ float d_Z    [kNH * kBT * kHD];
__device__ float d_ZPSI [kNH * kBT * kHD];
__device__ float d_P    [kNH * kBT * kHD];
__device__ float d_DY   [kNH * kBT * kHD];
__device__ float d_Q    [kNH * kBT * kHD];
__device__ float d_CP   [kNH * kB * kNC * kHD * kHD];
__device__ float d_Wc   [kNH * kB * kNC * kHD * kHD];
__device__ float d_SX   [kNH * kBT];
__device__ float d_G    [kNH * kHD * kHD];
__device__ float d_G2   [kNH * kHD * kHD];
__device__ float d_g1   [kNH * kHD];
__device__ float d_v2   [kNH * kHD];
__device__ float d_vbs  [kNH * kHD];
__device__ float d_S2   [kNH];
__device__ float d_SBS  [kNH];
__device__ int   d_flagH[kNH];        // per-head fast-path flag (written fresh each run)

// ---------------- f32x2 helpers ----------------
__device__ __forceinline__ ull fma2(ull a, ull b, ull c) {
    ull d;
    asm("fma.rn.f32x2 %0, %1, %2, %3;" : "=l"(d) : "l"(a), "l"(b), "l"(c));
    return d;
}
__device__ __forceinline__ ull pack2(float lo, float hi) {
    ull r;
    asm("mov.b64 %0, {%1, %2};" : "=l"(r) : "f"(lo), "f"(hi));
    return r;
}
__device__ __forceinline__ float hsum2(ull v) {
    float lo, hi;
    asm("mov.b64 {%0, %1}, %2;" : "=f"(lo), "=f"(hi) : "l"(v));
    return lo + hi;
}
__device__ __forceinline__ float warpsum(float v) {
    #pragma unroll
    for (int o = 16; o > 0; o >>= 1) v += __shfl_xor_sync(0xFFFFFFFFu, v, o);
    return v;
}

// ---------------- prep: G/G2 slices (y<8), rowstats+flag (y==8) ----------------
__global__ void __launch_bounds__(256) prep_kernel(const float* __restrict__ g,
                                                   const float* __restrict__ s,
                                                   const float* __restrict__ b) {
    const int k = blockIdx.x;
    const int y = blockIdx.y;
    const int tid = threadIdx.x;

    if (y < 8) {
        __shared__ float gsh[128 * 33];
        __shared__ float wsh[32];
        const int mode = y >> 2;           // 0 -> G, 1 -> G2
        const int rb = (y & 3) * 32;       // output row base
        const int tx = tid & 15, ty = tid >> 4;
        float acc[2][8];
        #pragma unroll
        for (int r = 0; r < 2; r++)
            #pragma unroll
            for (int c = 0; c < 8; c++) acc[r][c] = 0.f;

        for (int d0 = 0; d0 < kD; d0 += 32) {
            for (int f = tid; f < 128 * 32; f += 256) {
                int i = f >> 5, dd = f & 31;
                gsh[i * 33 + dd] = g[(size_t)(k * kHD + i) * kD + d0 + dd];
            }
            if (tid < 32) {
                float sv = s[k * kD + d0 + tid];
                wsh[tid] = mode ? sv * sv : 1.0f;
            }
            __syncthreads();
            #pragma unroll 4
            for (int dd = 0; dd < 32; dd++) {
                float wv = wsh[dd];
                float a0 = gsh[(rb + ty * 2 + 0) * 33 + dd] * wv;
                float a1 = gsh[(rb + ty * 2 + 1) * 33 + dd] * wv;
                float bb[8];
                #pragma unroll
                for (int c = 0; c < 8; c++) bb[c] = gsh[(tx * 8 + c) * 33 + dd];
                #pragma unroll
                for (int c = 0; c < 8; c++) {
                    acc[0][c] = fmaf(a0, bb[c], acc[0][c]);
                    acc[1][c] = fmaf(a1, bb[c], acc[1][c]);
                }
            }
            __syncthreads();
        }
        float* dst = (mode ? d_G2 : d_G) + k * kHD * kHD;
        #pragma unroll
        for (int r = 0; r < 2; r++)
            #pragma unroll
            for (int c = 0; c < 8; c++)
                dst[(rb + ty * 2 + r) * kHD + tx * 8 + c] = acc[r][c];
    } else {
        if (tid < 128) {
            float a1 = 0.f, a2 = 0.f, a3 = 0.f;
            const float* grow = g + (size_t)(k * kHD + tid) * kD;
            const float* srow = s + k * kD;
            const float* brow = b + k * kD;
            for (int d = 0; d < kD; d++) {
                float gv = grow[d], sv = srow[d], bv = brow[d];
                a1 += gv;
                a2 = fmaf(gv, sv * sv, a2);
                a3 = fmaf(gv, bv * sv, a3);
            }
            d_g1[k * kHD + tid]  = a1;
            d_v2[k * kHD + tid]  = a2;
            d_vbs[k * kHD + tid] = a3;
        }
        float s2p = 0.f, sbp = 0.f;
        int ok = 1;
        for (int d = tid; d < kD; d += 256) {
            float sv = s[k * kD + d], bv = b[k * kD + d];
            s2p = fmaf(sv, sv, s2p);
            sbp = fmaf(bv, sv, sbp);
            ok &= (sv == 1.0f) && (bv == 0.0f);
        }
        __shared__ float red[512];
        __shared__ int oksh;
        if (tid == 0) oksh = 1;
        red[tid] = s2p; red[256 + tid] = sbp;
        __syncthreads();
        if (!__all_sync(0xFFFFFFFFu, ok) && (tid & 31) == 0) atomicAnd(&oksh, 0);
        for (int o = 128; o > 0; o >>= 1) {
            if (tid < o) { red[tid] += red[tid + o]; red[256 + tid] += red[256 + tid + o]; }
            __syncthreads();
        }
        if (tid == 0) { d_S2[k] = red[0]; d_SBS[k] = red[256]; d_flagH[k] = oksh; }
    }
}

// ---------------- SX[k][bt] = sum_d X[bt][d]*s[k][d] ----------------
__global__ void sx_kernel(const float* __restrict__ X, const float* __restrict__ s) {
    const int bt = blockIdx.x;
    const int w = threadIdx.x >> 5;
    const int lane = threadIdx.x & 31;
    float acc = 0.f;
    for (int d0 = lane * 4; d0 < kD; d0 += 128) {
        float4 xv = *(const float4*)&X[bt * kD + d0];
        float4 sv = *(const float4*)&s[w * kD + d0];
        acc = fmaf(xv.x, sv.x, acc);
        acc = fmaf(xv.y, sv.y, acc);
        acc = fmaf(xv.z, sv.z, acc);
        acc = fmaf(xv.w, sv.w, acc);
    }
    acc = warpsum(acc);
    if (lane == 0) d_SX[w * kBT + bt] = acc;
}

// ---------------- projection GEMMs ----------------
__global__ void __launch_bounds__(256) gemm_proj_kernel(const float* __restrict__ X,
                                                        const float* __restrict__ phi,
                                                        const float* __restrict__ psi,
                                                        const float* __restrict__ g,
                                                        const float* __restrict__ s) {
    const int which = blockIdx.z % 3;
    const int head  = blockIdx.z / 3;
    const int m0 = blockIdx.y * 128;
    __shared__ float As[16 * GP];
    __shared__ float Bs[16 * GP];
    const int tid = threadIdx.x;
    const int tx = tid & 15, ty = tid >> 4;
    ull acc2[8][4];
    #pragma unroll
    for (int r = 0; r < 8; r++)
        #pragma unroll
        for (int c = 0; c < 4; c++) acc2[r][c] = 0ULL;

    const float* Bsrc = (which == 0) ? phi : psi;

    for (int k0 = 0; k0 < kD; k0 += 16) {
        {
            int m = tid >> 2, kq = tid & 3;
            #pragma unroll
            for (int h2 = 0; h2 < 2; h2++) {
                int mm = m + h2 * 64;
                float4 v = *(const float4*)&X[(size_t)(m0 + mm) * kD + k0 + kq * 4];
                As[(kq * 4 + 0) * GP + mm] = v.x;
                As[(kq * 4 + 1) * GP + mm] = v.y;
                As[(kq * 4 + 2) * GP + mm] = v.z;
                As[(kq * 4 + 3) * GP + mm] = v.w;
            }
        }
        if (which < 2) {
            int f = tid;
            #pragma unroll
            for (int it = 0; it < 2; it++, f += 256) {
                int kk = f >> 5, n4 = f & 31;
                float4 v = *(const float4*)&Bsrc[(size_t)(head * kD + k0 + kk) * kHD + n4 * 4];
                *(float4*)&Bs[kk * GP + n4 * 4] = v;
            }
        } else {
            int f = tid;
            #pragma unroll
            for (int it = 0; it < 2; it++, f += 256) {
                int jj = f >> 2, kq = f & 3;
                float4 gv = *(const float4*)&g[(size_t)(head * kHD + jj) * kD + k0 + kq * 4];
                float4 sv = *(const float4*)&s[head * kD + k0 + kq * 4];
                Bs[(kq * 4 + 0) * GP + jj] = gv.x * sv.x;
                Bs[(kq * 4 + 1) * GP + jj] = gv.y * sv.y;
                Bs[(kq * 4 + 2) * GP + jj] = gv.z * sv.z;
                Bs[(kq * 4 + 3) * GP + jj] = gv.w * sv.w;
            }
        }
        __syncthreads();
        #pragma unroll
        for (int kk = 0; kk < 16; kk++) {
            float a[8];
            *(float4*)&a[0]  = *(const float4*)&As[kk * GP + ty * 8];
            *(float4*)&a[4]  = *(const float4*)&As[kk * GP + ty * 8 + 4];
            ulonglong2 b0 = *(const ulonglong2*)&Bs[kk * GP + tx * 8];
            ulonglong2 b1 = *(const ulonglong2*)&Bs[kk * GP + tx * 8 + 4];
            #pragma unroll
            for (int r = 0; r < 8; r++) {
                ull a2 = pack2(a[r], a[r]);
                acc2[r][0] = fma2(a2, b0.x, acc2[r][0]);
                acc2[r][1] = fma2(a2, b0.y, acc2[r][1]);
                acc2[r][2] = fma2(a2, b1.x, acc2[r][2]);
                acc2[r][3] = fma2(a2, b1.y, acc2[r][3]);
            }
        }
        __syncthreads();
    }
    float* Cdst = ((which == 0) ? d_Z : (which == 1) ? d_ZPSI : d_P) + (size_t)head * kBT * kHD;
    #pragma unroll
    for (int r = 0; r < 8; r++) {
        int m = m0 + ty * 8 + r;
        *(ulonglong2*)&Cdst[(size_t)m * kHD + tx * 8]     = make_ulonglong2(acc2[r][0], acc2[r][1]);
        *(ulonglong2*)&Cdst[(size_t)m * kHD + tx * 8 + 4] = make_ulonglong2(acc2[r][2], acc2[r][3]);
    }
}

// ---------------- scan: one CTA per (head,batch), 512 threads; emits DY ----------------
// Thread map: j = tid>>2 (column 0..127), q = tid&3 (row quarter, 32 rows).
constexpr int SCAN_SMEM_FLOATS =
    128 * PITCH + 3 * 128 + 2 * 128 + 7 * 128 + 16 + 16 + 16 + 8;
constexpr int SCAN_SMEM_BYTES = SCAN_SMEM_FLOATS * 4;

__global__ void __launch_bounds__(512, 1) scan_kernel(const float* __restrict__ W0,
                                                      const float* __restrict__ Gsrc) {
    extern __shared__ float sm[];
    float* G2sh   = sm;
    float* zsh    = G2sh + 128 * PITCH;   // 3 x 128
    float* Psh    = zsh + 384;            // 2 x 128
    float* ysh    = Psh + 256;
    float* Gysh   = ysh + 128;
    float* G2ysh  = Gysh + 128;
    float* dysh   = G2ysh + 128;
    float* g1sh   = dysh + 128;
    float* v2sh   = g1sh + 128;
    float* vbssh  = v2sh + 128;
    float* dparts = vbssh + 128;   // 16: [which*4 + part]
    float* wsumA  = dparts + 16;   // su2 partials (16 warps)
    float* wsumB  = wsumA + 16;    // q2 partials
    float* sxs    = wsumB + 16;

    const int k = blockIdx.x;
    const int b = blockIdx.y;
    const int tid = threadIdx.x;
    const int j = tid >> 2;
    const int q = tid & 3;
    const int seg = q * 32;
    const int wid = tid >> 5;
    const int lane = tid & 31;
    const bool fast = (d_flagH[0] & d_flagH[1] & d_flagH[2] &
                       d_flagH[3] & d_flagH[4] & d_flagH[5]) != 0;

    if (!fast) {
        for (int idx = tid; idx < kHD * kHD; idx += 512)
            G2sh[(idx >> 7) * PITCH + (idx & 127)] = d_G2[k * kHD * kHD + idx];
    }
    const int tb = k * kBT + b * kT;
    const int seqbase = tb * kHD;
    if (tid < 128) {
        g1sh[tid]  = d_g1[k * kHD + tid];
        v2sh[tid]  = d_v2[k * kHD + tid];
        vbssh[tid] = d_vbs[k * kHD + tid];
        dysh[tid]  = 0.f;
        zsh[2 * 128 + tid] = 0.f;      // prev buffer at t=0 (dy=0 -> no-op update)
        zsh[tid]  = d_Z[seqbase + tid];
        Psh[tid]  = d_P[seqbase + tid];
        if (tid == 0) sxs[0] = d_SX[tb];
    }
    const float S2v  = d_S2[k];
    const float SBSv = d_SBS[k];

    // W: column j, rows seg..seg+31 (16 f32x2). G: row j, cols seg..seg+31.
    ull W2[16], Gr[16];
    {
        const float* wsrc = W0 + (size_t)k * kHD * kHD;
        #pragma unroll
        for (int p = 0; p < 16; p++)
            W2[p] = pack2(wsrc[(size_t)(seg + 2 * p) * kHD + j],
                          wsrc[(size_t)(seg + 2 * p + 1) * kHD + j]);
        const ulonglong2* grow = (const ulonglong2*)(Gsrc + (size_t)(k * kHD + j) * kHD + seg);
        #pragma unroll
        for (int p = 0; p < 8; p++) {
            ulonglong2 v = grow[p];
            Gr[2 * p] = v.x; Gr[2 * p + 1] = v.y;
        }
    }
    __syncthreads();

    const float cc = (float)kNH / (float)kD;
    const float invD = 1.f / (float)kD;
    int prevb = 2, curb = 0, nextb = 1;

    for (int t = 0; t < kT; ++t) {
        const int cur2 = t & 1;
        const int nb2 = cur2 ^ 1;
        const float dyO = dysh[j];
        const ull dyn2 = pack2(-dyO, -dyO);

        // prefetch next token (stashed at end of stage B)
        float nz = 0.f, nP = 0.f, nsx = 0.f;
        if (t + 1 < kT) {
            int pb = seqbase + (t + 1) * kHD;
            if (tid < 128) nz = d_Z[pb + tid];
            else if (tid < 256) nP = d_P[pb + tid - 128];
            if (tid == 384) nsx = d_SX[tb + t + 1];
        }

        // ---- Stage A: W -= z_{t-1} dy^T ; y = z_t @ W ----
        float ypart;
        {
            const ulonglong2* zo2 = (const ulonglong2*)(zsh + prevb * 128 + seg);
            const ulonglong2* zc2 = (const ulonglong2*)(zsh + curb * 128 + seg);
            ull ya0 = 0ULL, ya1 = 0ULL, ya2 = 0ULL, ya3 = 0ULL;
            #pragma unroll
            for (int p = 0; p < 8; p += 2) {
                ulonglong2 a0 = zo2[p], c0 = zc2[p];
                ulonglong2 a1 = zo2[p + 1], c1 = zc2[p + 1];
                ull w0 = fma2(a0.x, dyn2, W2[2 * p]);
                ull w1 = fma2(a0.y, dyn2, W2[2 * p + 1]);
                ull w2 = fma2(a1.x, dyn2, W2[2 * p + 2]);
                ull w3 = fma2(a1.y, dyn2, W2[2 * p + 3]);
                W2[2 * p] = w0; W2[2 * p + 1] = w1; W2[2 * p + 2] = w2; W2[2 * p + 3] = w3;
                ya0 = fma2(c0.x, w0, ya0);
                ya1 = fma2(c0.y, w1, ya1);
                ya2 = fma2(c1.x, w2, ya2);
                ya3 = fma2(c1.y, w3, ya3);
            }
            ypart = hsum2(ya0) + hsum2(ya1) + hsum2(ya2) + hsum2(ya3);
            ypart += __shfl_xor_sync(0xFFFFFFFFu, ypart, 1);
            ypart += __shfl_xor_sync(0xFFFFFFFFu, ypart, 2);
            if (q == 0) ysh[j] = ypart;
        }
        __syncthreads();   // S1: y ready

        // ---- Stage B: Gy (+G2y), su2/q2 partials, 4 scalar dots, stash ----
        {
            const ulonglong2* y2 = (const ulonglong2*)(ysh + seg);
            ull ga0 = 0ULL, ga1 = 0ULL, ga2 = 0ULL, ga3 = 0ULL;
            #pragma unroll
            for (int p = 0; p < 8; p += 2) {
                ulonglong2 y0 = y2[p], y1 = y2[p + 1];
                ga0 = fma2(Gr[2 * p], y0.x, ga0);
                ga1 = fma2(Gr[2 * p + 1], y0.y, ga1);
                ga2 = fma2(Gr[2 * p + 2], y1.x, ga2);
                ga3 = fma2(Gr[2 * p + 3], y1.y, ga3);
            }
            float gpart = hsum2(ga0) + hsum2(ga1) + hsum2(ga2) + hsum2(ga3);
            gpart += __shfl_xor_sync(0xFFFFFFFFu, gpart, 1);
            gpart += __shfl_xor_sync(0xFFFFFFFFu, gpart, 2);
            float g2part = gpart;
            if (!fast) {
                const ulonglong2* g2r = (const ulonglong2*)(G2sh + j * PITCH + seg);
                ull h0 = 0ULL, h1 = 0ULL, h2 = 0ULL, h3 = 0ULL;
                #pragma unroll
                for (int p = 0; p < 8; p += 2) {
                    ulonglong2 gv0 = g2r[p], gv1 = g2r[p + 1];
                    ulonglong2 y0 = y2[p], y1 = y2[p + 1];
                    h0 = fma2(gv0.x, y0.x, h0);
                    h1 = fma2(gv0.y, y0.y, h1);
                    h2 = fma2(gv1.x, y1.x, h2);
                    h3 = fma2(gv1.y, y1.y, h3);
                }
                g2part = hsum2(h0) + hsum2(h1) + hsum2(h2) + hsum2(h3);
                g2part += __shfl_xor_sync(0xFFFFFFFFu, g2part, 1);
                g2part += __shfl_xor_sync(0xFFFFFFFFu, g2part, 2);
            }
            if (q == 0) { Gysh[j] = gpart; G2ysh[j] = g2part; }

            // su2 / q2 warp partials (only q==0 lanes contribute)
            float yv0 = (q == 0) ? ypart : 0.f;
            float su2p = warpsum(gpart * yv0);
            if (lane == 0) wsumA[wid] = su2p;
            if (!fast) {
                float q2p = warpsum(g2part * yv0);
                if (lane == 0) wsumB[wid] = q2p;
            }

            // 4 scalar dots spread over 16 warps: which = wid>>2, 32-seg = wid&3
            {
                const int which = wid >> 2;
                const int s32 = (wid & 3) * 32 + lane;
                const float* vsel = (which == 0) ? g1sh
                                  : (which == 1) ? (Psh + cur2 * 128)
                                  : (which == 2) ? v2sh : vbssh;
                float v = warpsum(vsel[s32] * ysh[s32]);
                if (lane == 0) dparts[wid] = v;
            }

            // stash prefetched token (distinct buffers — no race with readers)
            if (t + 1 < kT) {
                if (tid < 128) zsh[nextb * 128 + tid] = nz;
                else if (tid < 256) Psh[nb2 * 128 + tid - 128] = nP;
                if (tid == 384) sxs[nb2] = nsx;
            }
        }
        __syncthreads();   // S2: dots + Gy ready

        // ---- Stage E: scalars, dy ----
        if (tid < 128) {
            const float g1y  = dparts[0] + dparts[1] + dparts[2] + dparts[3];
            const float Pty  = dparts[4] + dparts[5] + dparts[6] + dparts[7];
            const float v2y  = dparts[8] + dparts[9] + dparts[10] + dparts[11];
            const float vbsy = dparts[12] + dparts[13] + dparts[14] + dparts[15];
            float su2 = 0.f;
            #pragma unroll
            for (int w = 0; w < 16; w++) su2 += wsumA[w];
            float q2 = su2;
            if (!fast) {
                q2 = 0.f;
                #pragma unroll
                for (int w = 0; w < 16; w++) q2 += wsumB[w];
            }
            const float SXt = sxs[cur2];

            const float mu = g1y * invD;
            const float var = su2 * invD - mu * mu;
            const float rr = rsqrtf(var + kEPS);
            const float r2 = rr * rr;
            const float mdn  = (cc * invD) * (rr * (v2y - mu * S2v) + SBSv - SXt);
            const float mdnn = (cc * invD) * (r2 * (q2 - 2.f * mu * v2y + mu * mu * S2v)
                                              + rr * (vbsy - mu * SBSv)
                                              - rr * (Pty - mu * SXt));
            const float a1 = cc * r2;
            const float a2 = -r2 * mdnn;
            const float a3 = -cc * rr;
            const float a4 = -cc * r2 * mu;
            const float a5 = cc * rr;
            const float a6 = rr * (mdnn * rr * mu - mdn);
            const int i = tid;
            float gy = Gysh[i];
            float g2y = fast ? gy : G2ysh[i];
            float dyv = a1 * g2y + a2 * gy + a3 * Psh[cur2 * 128 + i]
                      + a4 * v2sh[i] + a5 * vbssh[i] + a6 * g1sh[i];
            dysh[i] = dyv;
            d_DY[seqbase + t * kHD + i] = dyv;
        }
        __syncthreads();   // S3: dy ready

        int tmp = prevb; prevb = curb; curb = nextb; nextb = tmp;
    }
}

// ---------------- CP_c = Z_c^T @ DY_c ; grid (kNC, 12) ----------------
__global__ void __launch_bounds__(256) chunkA_kernel() {
    const int c = blockIdx.x;
    const int kb = blockIdx.y;
    const int base = (kb >> 1) * kBT + (kb & 1) * kT + c * kC;
    __shared__ float As[16 * GP];
    __shared__ float Bs[16 * GP];
    const int tid = threadIdx.x;
    const int tx = tid & 15, ty = tid >> 4;
    float acc[8][8];
    #pragma unroll
    for (int r = 0; r < 8; r++)
        #pragma unroll
        for (int q = 0; q < 8; q++) acc[r][q] = 0.f;

    for (int r0 = 0; r0 < kC; r0 += 16) {
        int f = tid;
        #pragma unroll
        for (int it = 0; it < 2; it++, f += 256) {
            int kk = f >> 5, c4 = f & 31;
            *(float4*)&As[kk * GP + c4 * 4] =
                *(const float4*)&d_Z[(size_t)(base + r0 + kk) * kHD + c4 * 4];
            *(float4*)&Bs[kk * GP + c4 * 4] =
                *(const float4*)&d_DY[(size_t)(base + r0 + kk) * kHD + c4 * 4];
        }
        __syncthreads();
        #pragma unroll
        for (int kk = 0; kk < 16; kk++) {
            float a[8], bb[8];
            *(float4*)&a[0]  = *(const float4*)&As[kk * GP + ty * 8];
            *(float4*)&a[4]  = *(const float4*)&As[kk * GP + ty * 8 + 4];
            *(float4*)&bb[0] = *(const float4*)&Bs[kk * GP + tx * 8];
            *(float4*)&bb[4] = *(const float4*)&Bs[kk * GP + tx * 8 + 4];
            #pragma unroll
            for (int r = 0; r < 8; r++)
                #pragma unroll
                for (int q = 0; q < 8; q++) acc[r][q] = fmaf(a[r], bb[q], acc[r][q]);
        }
        __syncthreads();
    }
    float* dst = d_CP + (size_t)(kb * kNC + c) * kHD * kHD;
    #pragma unroll
    for (int r = 0; r < 8; r++) {
        int i = ty * 8 + r;
        *(float4*)&dst[(size_t)i * kHD + tx * 8]     = make_float4(acc[r][0], acc[r][1], acc[r][2], acc[r][3]);
        *(float4*)&dst[(size_t)i * kHD + tx * 8 + 4] = make_float4(acc[r][4], acc[r][5], acc[r][6], acc[r][7]);
    }
}

// ---------------- W_c prefix ; grid (12) ----------------
__global__ void __launch_bounds__(256) prefix_kernel(const float* __restrict__ W0) {
    const int kb = blockIdx.x;
    const int k = kb >> 1;
    const int tid = threadIdx.x;
    float w[64];
    #pragma unroll
    for (int e = 0; e < 64; e++) w[e] = W0[(size_t)k * kHD * kHD + e * 256 + tid];
    for (int c = 0; c < kNC; c++) {
        float* dst = d_Wc + (size_t)(kb * kNC + c) * kHD * kHD;
        #pragma unroll
        for (int e = 0; e < 64; e++) dst[e * 256 + tid] = w[e];
        if (c < kNC - 1) {
            const float* cp = d_CP + (size_t)(kb * kNC + c) * kHD * kHD;
            #pragma unroll
            for (int e = 0; e < 64; e++) w[e] -= cp[e * 256 + tid];
        }
    }
}

// ---------------- Q_c = Zpsi_c@W_c - tril(Zpsi_c Z_c^T)@DY_c ; grid (kNC, 12) ----------------
constexpr int QR_SMEM_FLOATS = 128 * PITCH + 2 * 16 * GP;
constexpr int QR_SMEM_BYTES = QR_SMEM_FLOATS * 4;

__global__ void __launch_bounds__(256) qrecon_kernel() {
    const int c = blockIdx.x;
    const int kb = blockIdx.y;
    const int base = (kb >> 1) * kBT + (kb & 1) * kT + c * kC;
    extern __shared__ float qs[];
    float* Msh = qs;                 // tril(S) stored transposed: Msh[r*PITCH + t]
    float* As  = Msh + 128 * PITCH;
    float* Bs  = As + 16 * GP;
    const int tid = threadIdx.x;
    const int tx = tid & 15, ty = tid >> 4;
    const int m = tid >> 2, kq = tid & 3;

    float acc[8][8];
    #pragma unroll
    for (int r = 0; r < 8; r++)
        #pragma unroll
        for (int q = 0; q < 8; q++) acc[r][q] = 0.f;

    // ---- Phase 1: S = Zpsi_c @ Z_c^T ----
    for (int d0 = 0; d0 < kHD; d0 += 16) {
        #pragma unroll
        for (int h2 = 0; h2 < 2; h2++) {
            int mm = m + h2 * 64;
            float4 va = *(const float4*)&d_ZPSI[(size_t)(base + mm) * kHD + d0 + kq * 4];
            As[(kq * 4 + 0) * GP + mm] = va.x;
            As[(kq * 4 + 1) * GP + mm] = va.y;
            As[(kq * 4 + 2) * GP + mm] = va.z;
            As[(kq * 4 + 3) * GP + mm] = va.w;
            float4 vb = *(const float4*)&d_Z[(size_t)(base + mm) * kHD + d0 + kq * 4];
            Bs[(kq * 4 + 0) * GP + mm] = vb.x;
            Bs[(kq * 4 + 1) * GP + mm] = vb.y;
            Bs[(kq * 4 + 2) * GP + mm] = vb.z;
            Bs[(kq * 4 + 3) * GP + mm] = vb.w;
        }
        __syncthreads();
        #pragma unroll
        for (int kk = 0; kk < 16; kk++) {
            float a[8], bb[8];
            *(float4*)&a[0]  = *(const float4*)&As[kk * GP + ty * 8];
            *(float4*)&a[4]  = *(const float4*)&As[kk * GP + ty * 8 + 4];
            *(float4*)&bb[0] = *(const float4*)&Bs[kk * GP + tx * 8];
            *(float4*)&bb[4] = *(const float4*)&Bs[kk * GP + tx * 8 + 4];
            #pragma unroll
            for (int r = 0; r < 8; r++)
                #pragma unroll
                for (int q = 0; q < 8; q++) acc[r][q] = fmaf(a[r], bb[q], acc[r][q]);
        }
        __syncthreads();
    }
    // masked transposed store: Msh[r][t] = (r <= t) ? S[t][r] : 0
    #pragma unroll
    for (int r = 0; r < 8; r++) {
        int t = ty * 8 + r;
        #pragma unroll
        for (int q = 0; q < 8; q++) {
            int rr = tx * 8 + q;
            Msh[rr * PITCH + t] = (rr <= t) ? acc[r][q] : 0.f;
        }
    }
    #pragma unroll
    for (int r = 0; r < 8; r++)
        #pragma unroll
        for (int q = 0; q < 8; q++) acc[r][q] = 0.f;
    __syncthreads();

    // ---- Phase 2: acc = Zpsi_c @ W_c ----
    const float* Wc = d_Wc + (size_t)(kb * kNC + c) * kHD * kHD;
    for (int d0 = 0; d0 < kHD; d0 += 16) {
        #pragma unroll
        for (int h2 = 0; h2 < 2; h2++) {
            int mm = m + h2 * 64;
            float4 va = *(const float4*)&d_ZPSI[(size_t)(base + mm) * kHD + d0 + kq * 4];
            As[(kq * 4 + 0) * GP + mm] = va.x;
            As[(kq * 4 + 1) * GP + mm] = va.y;
            As[(kq * 4 + 2) * GP + mm] = va.z;
            As[(kq * 4 + 3) * GP + mm] = va.w;
        }
        {
            int f = tid;
            #pragma unroll
            for (int it = 0; it < 2; it++, f += 256) {
                int kk = f >> 5, c4 = f & 31;
                *(float4*)&Bs[kk * GP + c4 * 4] =
                    *(const float4*)&Wc[(size_t)(d0 + kk) * kHD + c4 * 4];
            }
        }
        __syncthreads();
        #pragma unroll
        for (int kk = 0; kk < 16; kk++) {
            float a[8], bb[8];
            *(float4*)&a[0]  = *(const float4*)&As[kk * GP + ty * 8];
            *(float4*)&a[4]  = *(const float4*)&As[kk * GP + ty * 8 + 4];
            *(float4*)&bb[0] = *(const float4*)&Bs[kk * GP + tx * 8];
            *(float4*)&bb[4] = *(const float4*)&Bs[kk * GP + tx * 8 + 4];
            #pragma unroll
            for (int r = 0; r < 8; r++)
                #pragma unroll
                for (int q = 0; q < 8; q++) acc[r][q] = fmaf(a[r], bb[q], acc[r][q]);
        }
        __syncthreads();
    }

    // ---- Phase 3: acc -= tril(S) @ DY_c ----
    for (int r0 = 0; r0 < kC; r0 += 16) {
        int f = tid;
        #pragma unroll
        for (int it = 0; it < 2; it++, f += 256) {
            int kk = f >> 5, c4 = f & 31;
            *(float4*)&Bs[kk * GP + c4 * 4] =
                *(const float4*)&d_DY[(size_t)(base + r0 + kk) * kHD + c4 * 4];
        }
        __syncthreads();
        #pragma unroll
        for (int kk = 0; kk < 16; kk++) {
            float a[8], bb[8];
            *(float4*)&a[0]  = *(const float4*)&Msh[(r0 + kk) * PITCH + ty * 8];
            *(float4*)&a[4]  = *(const float4*)&Msh[(r0 + kk) * PITCH + ty * 8 + 4];
            *(float4*)&bb[0] = *(const float4*)&Bs[kk * GP + tx * 8];
            *(float4*)&bb[4] = *(const float4*)&Bs[kk * GP + tx * 8 + 4];
            #pragma unroll
            for (int r = 0; r < 8; r++)
                #pragma unroll
                for (int q = 0; q < 8; q++) acc[r][q] = fmaf(-a[r], bb[q], acc[r][q]);
        }
        __syncthreads();
    }

    #pragma unroll
    for (int r = 0; r < 8; r++) {
        int t = base + ty * 8 + r;
        *(float4*)&d_Q[(size_t)t * kHD + tx * 8]     = make_float4(acc[r][0], acc[r][1], acc[r][2], acc[r][3]);
        *(float4*)&d_Q[(size_t)t * kHD + tx * 8 + 4] = make_float4(acc[r][4], acc[r][5], acc[r][6], acc[r][7]);
    }
}

// ---------------- output GEMM ----------------
__global__ void __launch_bounds__(256) gemm_out_kernel(const float* __restrict__ h,
                                                       float* __restrict__ out) {
    const int n0 = blockIdx.x * 128;
    const int m0 = blockIdx.y * 128;
    __shared__ float As[16 * GP];
    __shared__ float Bs[16 * GP];
    const int tid = threadIdx.x;
    const int tx = tid & 15, ty = tid >> 4;
    ull acc2[8][4];
    #pragma unroll
    for (int r = 0; r < 8; r++)
        #pragma unroll
        for (int c = 0; c < 4; c++) acc2[r][c] = 0ULL;

    for (int k0 = 0; k0 < kNH * kHD; k0 += 16) {
        const int head = k0 >> 7;
        const int j0 = k0 & 127;
        const float* Aq = d_Q + (size_t)head * kBT * kHD;
        {
            int m = tid >> 2, kq = tid & 3;
            #pragma unroll
            for (int h2 = 0; h2 < 2; h2++) {
                int mm = m + h2 * 64;
                float4 v = *(const float4*)&Aq[(size_t)(m0 + mm) * kHD + j0 + kq * 4];
                As[(kq * 4 + 0) * GP + mm] = v.x;
                As[(kq * 4 + 1) * GP + mm] = v.y;
                As[(kq * 4 + 2) * GP + mm] = v.z;
                As[(kq * 4 + 3) * GP + mm] = v.w;
            }
        }
        {
            int f = tid;
            #pragma unroll
            for (int it = 0; it < 2; it++, f += 256) {
                int kk = f >> 5, n4 = f & 31;
                float4 v = *(const float4*)&h[(size_t)(k0 + kk) * kD + n0 + n4 * 4];
                *(float4*)&Bs[kk * GP + n4 * 4] = v;
            }
        }
        __syncthreads();
        #pragma unroll
        for (int kk = 0; kk < 16; kk++) {
            float a[8];
            *(float4*)&a[0]  = *(const float4*)&As[kk * GP + ty * 8];
            *(float4*)&a[4]  = *(const float4*)&As[kk * GP + ty * 8 + 4];
            ulonglong2 b0 = *(const ulonglong2*)&Bs[kk * GP + tx * 8];
            ulonglong2 b1 = *(const ulonglong2*)&Bs[kk * GP + tx * 8 + 4];
            #pragma unroll
            for (int r = 0; r < 8; r++) {
                ull a2 = pack2(a[r], a[r]);
                acc2[r][0] = fma2(a2, b0.x, acc2[r][0]);
                acc2[r][1] = fma2(a2, b0.y, acc2[r][1]);
                acc2[r][2] = fma2(a2, b1.x, acc2[r][2]);
                acc2[r][3] = fma2(a2, b1.y, acc2[r][3]);
            }
        }
        __syncthreads();
    }
    #pragma unroll
    for (int r = 0; r < 8; r++) {
        int mm = m0 + ty * 8 + r;
        *(ulonglong2*)&out[(size_t)mm * kD + n0 + tx * 8]     = make_ulonglong2(acc2[r][0], acc2[r][1]);
        *(ulonglong2*)&out[(size_t)mm * kD + n0 + tx * 8 + 4] = make_ulonglong2(acc2[r][2], acc2[r][3]);
    }
}

// ---------------- launch ----------------
extern "C" void kernel_launch(void* const* d_in, const int* in_sizes, int n_in,
                              void* d_out, int out_size) {
    const float* X   = (const float*)d_in[0];
    const float* psi = (const float*)d_in[1];
    const float* phi = (const float*)d_in[2];
    const float* W0  = (const float*)d_in[3];
    const float* g   = (const float*)d_in[4];
    const float* h   = (const float*)d_in[5];
    const float* lns = (const float*)d_in[6];
    const float* lnb = (const float*)d_in[7];
    float* out = (float*)d_out;
    (void)in_sizes; (void)n_in; (void)out_size;

    float* gptr = nullptr;
    cudaGetSymbolAddress((void**)&gptr, d_G);

    cudaFuncSetAttribute(scan_kernel, cudaFuncAttributeMaxDynamicSharedMemorySize, SCAN_SMEM_BYTES);
    cudaFuncSetAttribute(qrecon_kernel, cudaFuncAttributeMaxDynamicSharedMemorySize, QR_SMEM_BYTES);

    prep_kernel<<<dim3(kNH, 9), 256>>>(g, lns, lnb);
    sx_kernel<<<kBT, 192>>>(X, lns);
    gemm_proj_kernel<<<dim3(1, kBT / 128, 3 * kNH), 256>>>(X, phi, psi, g, lns);
    scan_kernel<<<dim3(kNH, kB), 512, SCAN_SMEM_BYTES>>>(W0, gptr);
    chunkA_kernel<<<dim3(kNC, kNH * kB), 256>>>();
    prefix_kernel<<<kNH * kB, 256>>>(W0);
    qrecon_kernel<<<dim3(kNC, kNH * kB), 256, QR_SMEM_BYTES>>>();
    gemm_out_kernel<<<dim3(kD / 128, kBT / 128), 256>>>(h, out);
}

// round 14
// speedup vs baseline: 2.2435x; 2.2435x over previous
#include <cuda_runtime.h>
#include <cuda_bf16.h>

// ---------------- problem constants ----------------
constexpr int kNH = 6;
constexpr int kD  = 768;
constexpr int kHD = 128;
constexpr int kB  = 2;
constexpr int kT  = 2048;
constexpr int kBT = kB * kT;          // 4096
constexpr int kC  = 128;              // chunk size for Q reconstruction
constexpr int kNC = kT / kC;          // 16 chunks per sequence
constexpr float kEPS = 1e-6f;

constexpr int PITCH = 132;
constexpr int GP    = 132;

typedef unsigned long long ull;

// ---------------- device scratch ----------------
__device__ float d_Z    [kNH * kBT * kHD];
__device__ float d_ZPSI [kNH * kBT * kHD];
__device__ float d_P    [kNH * kBT * kHD];
__device__ float d_DY   [kNH * kBT * kHD];
__device__ float d_Q    [kNH * kBT * kHD];
__device__ float d_CP   [kNH * kB * kNC * kHD * kHD];
__device__ float d_Wc   [kNH * kB * kNC * kHD * kHD];
__device__ float d_SX   [kNH * kBT];
__device__ float d_G    [kNH * kHD * kHD];
__device__ float d_G2   [kNH * kHD * kHD];
__device__ float d_g1   [kNH * kHD];
__device__ float d_v2   [kNH * kHD];
__device__ float d_vbs  [kNH * kHD];
__device__ float d_S2   [kNH];
__device__ float d_SBS  [kNH];
__device__ int   d_flagH[kNH];        // per-head fast-path flag (written fresh each run)

// ---------------- f32x2 helpers ----------------
__device__ __forceinline__ ull fma2(ull a, ull b, ull c) {
    ull d;
    asm("fma.rn.f32x2 %0, %1, %2, %3;" : "=l"(d) : "l"(a), "l"(b), "l"(c));
    return d;
}
__device__ __forceinline__ ull pack2(float lo, float hi) {
    ull r;
    asm("mov.b64 %0, {%1, %2};" : "=l"(r) : "f"(lo), "f"(hi));
    return r;
}
__device__ __forceinline__ float hsum2(ull v) {
    float lo, hi;
    asm("mov.b64 {%0, %1}, %2;" : "=f"(lo), "=f"(hi) : "l"(v));
    return lo + hi;
}
__device__ __forceinline__ float warpsum(float v) {
    #pragma unroll
    for (int o = 16; o > 0; o >>= 1) v += __shfl_xor_sync(0xFFFFFFFFu, v, o);
    return v;
}

// ---------------- prep: G/G2 slices (y<8), rowstats+flag (y==8) ----------------
__global__ void __launch_bounds__(256) prep_kernel(const float* __restrict__ g,
                                                   const float* __restrict__ s,
                                                   const float* __restrict__ b) {
    const int k = blockIdx.x;
    const int y = blockIdx.y;
    const int tid = threadIdx.x;

    if (y < 8) {
        __shared__ float gsh[128 * 33];
        __shared__ float wsh[32];
        const int mode = y >> 2;           // 0 -> G, 1 -> G2
        const int rb = (y & 3) * 32;       // output row base
        const int tx = tid & 15, ty = tid >> 4;
        float acc[2][8];
        #pragma unroll
        for (int r = 0; r < 2; r++)
            #pragma unroll
            for (int c = 0; c < 8; c++) acc[r][c] = 0.f;

        for (int d0 = 0; d0 < kD; d0 += 32) {
            for (int f = tid; f < 128 * 32; f += 256) {
                int i = f >> 5, dd = f & 31;
                gsh[i * 33 + dd] = g[(size_t)(k * kHD + i) * kD + d0 + dd];
            }
            if (tid < 32) {
                float sv = s[k * kD + d0 + tid];
                wsh[tid] = mode ? sv * sv : 1.0f;
            }
            __syncthreads();
            #pragma unroll 4
            for (int dd = 0; dd < 32; dd++) {
                float wv = wsh[dd];
                float a0 = gsh[(rb + ty * 2 + 0) * 33 + dd] * wv;
                float a1 = gsh[(rb + ty * 2 + 1) * 33 + dd] * wv;
                float bb[8];
                #pragma unroll
                for (int c = 0; c < 8; c++) bb[c] = gsh[(tx * 8 + c) * 33 + dd];
                #pragma unroll
                for (int c = 0; c < 8; c++) {
                    acc[0][c] = fmaf(a0, bb[c], acc[0][c]);
                    acc[1][c] = fmaf(a1, bb[c], acc[1][c]);
                }
            }
            __syncthreads();
        }
        float* dst = (mode ? d_G2 : d_G) + k * kHD * kHD;
        #pragma unroll
        for (int r = 0; r < 2; r++)
            #pragma unroll
            for (int c = 0; c < 8; c++)
                dst[(rb + ty * 2 + r) * kHD + tx * 8 + c] = acc[r][c];
    } else {
        if (tid < 128) {
            float a1 = 0.f, a2 = 0.f, a3 = 0.f;
            const float* grow = g + (size_t)(k * kHD + tid) * kD;
            const float* srow = s + k * kD;
            const float* brow = b + k * kD;
            for (int d = 0; d < kD; d++) {
                float gv = grow[d], sv = srow[d], bv = brow[d];
                a1 += gv;
                a2 = fmaf(gv, sv * sv, a2);
                a3 = fmaf(gv, bv * sv, a3);
            }
            d_g1[k * kHD + tid]  = a1;
            d_v2[k * kHD + tid]  = a2;
            d_vbs[k * kHD + tid] = a3;
        }
        float s2p = 0.f, sbp = 0.f;
        int ok = 1;
        for (int d = tid; d < kD; d += 256) {
            float sv = s[k * kD + d], bv = b[k * kD + d];
            s2p = fmaf(sv, sv, s2p);
            sbp = fmaf(bv, sv, sbp);
            ok &= (sv == 1.0f) && (bv == 0.0f);
        }
        __shared__ float red[512];
        __shared__ int oksh;
        if (tid == 0) oksh = 1;
        red[tid] = s2p; red[256 + tid] = sbp;
        __syncthreads();
        if (!__all_sync(0xFFFFFFFFu, ok) && (tid & 31) == 0) atomicAnd(&oksh, 0);
        for (int o = 128; o > 0; o >>= 1) {
            if (tid < o) { red[tid] += red[tid + o]; red[256 + tid] += red[256 + tid + o]; }
            __syncthreads();
        }
        if (tid == 0) { d_S2[k] = red[0]; d_SBS[k] = red[256]; d_flagH[k] = oksh; }
    }
}

// ---------------- SX[k][bt] = sum_d X[bt][d]*s[k][d] ----------------
__global__ void sx_kernel(const float* __restrict__ X, const float* __restrict__ s) {
    const int bt = blockIdx.x;
    const int w = threadIdx.x >> 5;
    const int lane = threadIdx.x & 31;
    float acc = 0.f;
    for (int d0 = lane * 4; d0 < kD; d0 += 128) {
        float4 xv = *(const float4*)&X[bt * kD + d0];
        float4 sv = *(const float4*)&s[w * kD + d0];
        acc = fmaf(xv.x, sv.x, acc);
        acc = fmaf(xv.y, sv.y, acc);
        acc = fmaf(xv.z, sv.z, acc);
        acc = fmaf(xv.w, sv.w, acc);
    }
    acc = warpsum(acc);
    if (lane == 0) d_SX[w * kBT + bt] = acc;
}

// ---------------- projection GEMMs ----------------
__global__ void __launch_bounds__(256) gemm_proj_kernel(const float* __restrict__ X,
                                                        const float* __restrict__ phi,
                                                        const float* __restrict__ psi,
                                                        const float* __restrict__ g,
                                                        const float* __restrict__ s) {
    const int which = blockIdx.z % 3;
    const int head  = blockIdx.z / 3;
    const int m0 = blockIdx.y * 128;
    __shared__ float As[16 * GP];
    __shared__ float Bs[16 * GP];
    const int tid = threadIdx.x;
    const int tx = tid & 15, ty = tid >> 4;
    ull acc2[8][4];
    #pragma unroll
    for (int r = 0; r < 8; r++)
        #pragma unroll
        for (int c = 0; c < 4; c++) acc2[r][c] = 0ULL;

    const float* Bsrc = (which == 0) ? phi : psi;

    for (int k0 = 0; k0 < kD; k0 += 16) {
        {
            int m = tid >> 2, kq = tid & 3;
            #pragma unroll
            for (int h2 = 0; h2 < 2; h2++) {
                int mm = m + h2 * 64;
                float4 v = *(const float4*)&X[(size_t)(m0 + mm) * kD + k0 + kq * 4];
                As[(kq * 4 + 0) * GP + mm] = v.x;
                As[(kq * 4 + 1) * GP + mm] = v.y;
                As[(kq * 4 + 2) * GP + mm] = v.z;
                As[(kq * 4 + 3) * GP + mm] = v.w;
            }
        }
        if (which < 2) {
            int f = tid;
            #pragma unroll
            for (int it = 0; it < 2; it++, f += 256) {
                int kk = f >> 5, n4 = f & 31;
                float4 v = *(const float4*)&Bsrc[(size_t)(head * kD + k0 + kk) * kHD + n4 * 4];
                *(float4*)&Bs[kk * GP + n4 * 4] = v;
            }
        } else {
            int f = tid;
            #pragma unroll
            for (int it = 0; it < 2; it++, f += 256) {
                int jj = f >> 2, kq = f & 3;
                float4 gv = *(const float4*)&g[(size_t)(head * kHD + jj) * kD + k0 + kq * 4];
                float4 sv = *(const float4*)&s[head * kD + k0 + kq * 4];
                Bs[(kq * 4 + 0) * GP + jj] = gv.x * sv.x;
                Bs[(kq * 4 + 1) * GP + jj] = gv.y * sv.y;
                Bs[(kq * 4 + 2) * GP + jj] = gv.z * sv.z;
                Bs[(kq * 4 + 3) * GP + jj] = gv.w * sv.w;
            }
        }
        __syncthreads();
        #pragma unroll
        for (int kk = 0; kk < 16; kk++) {
            float a[8];
            *(float4*)&a[0]  = *(const float4*)&As[kk * GP + ty * 8];
            *(float4*)&a[4]  = *(const float4*)&As[kk * GP + ty * 8 + 4];
            ulonglong2 b0 = *(const ulonglong2*)&Bs[kk * GP + tx * 8];
            ulonglong2 b1 = *(const ulonglong2*)&Bs[kk * GP + tx * 8 + 4];
            #pragma unroll
            for (int r = 0; r < 8; r++) {
                ull a2 = pack2(a[r], a[r]);
                acc2[r][0] = fma2(a2, b0.x, acc2[r][0]);
                acc2[r][1] = fma2(a2, b0.y, acc2[r][1]);
                acc2[r][2] = fma2(a2, b1.x, acc2[r][2]);
                acc2[r][3] = fma2(a2, b1.y, acc2[r][3]);
            }
        }
        __syncthreads();
    }
    float* Cdst = ((which == 0) ? d_Z : (which == 1) ? d_ZPSI : d_P) + (size_t)head * kBT * kHD;
    #pragma unroll
    for (int r = 0; r < 8; r++) {
        int m = m0 + ty * 8 + r;
        *(ulonglong2*)&Cdst[(size_t)m * kHD + tx * 8]     = make_ulonglong2(acc2[r][0], acc2[r][1]);
        *(ulonglong2*)&Cdst[(size_t)m * kHD + tx * 8 + 4] = make_ulonglong2(acc2[r][2], acc2[r][3]);
    }
}

// ---------------- scan: one CTA per (head,batch), 256 threads, 2 barriers/step ----------------
// Thread map: j = tid>>1 (column), half = tid&1 (row half, 64 rows).
// dy is register-carried; stage E computed redundantly by all threads.
constexpr int SCAN_SMEM_FLOATS =
    128 * PITCH      // G2sh (generic path only)
    + 3 * 128        // zsh triple buffer
    + 2 * 128        // Psh double buffer
    + 4 * 128        // ysh, g1sh, v2sh, vbssh
    + 8 + 8 + 8 + 8; // dparts, wsumA, wsumB, sxs(+pad)
constexpr int SCAN_SMEM_BYTES = SCAN_SMEM_FLOATS * 4;

__global__ void __launch_bounds__(256, 1) scan_kernel(const float* __restrict__ W0,
                                                      const float* __restrict__ Gsrc) {
    extern __shared__ float sm[];
    float* G2sh   = sm;
    float* zsh    = G2sh + 128 * PITCH;   // 3 x 128
    float* Psh    = zsh + 384;            // 2 x 128
    float* ysh    = Psh + 256;
    float* g1sh   = ysh + 128;
    float* v2sh   = g1sh + 128;
    float* vbssh  = v2sh + 128;
    float* dparts = vbssh + 128;   // 8: [which*2 + seg]
    float* wsumA  = dparts + 8;    // su2 partials (8 warps)
    float* wsumB  = wsumA + 8;     // q2 partials
    float* sxs    = wsumB + 8;     // SX double buffer

    const int k = blockIdx.x;
    const int b = blockIdx.y;
    const int tid = threadIdx.x;
    const int j = tid >> 1;
    const int half = tid & 1;
    const int wid = tid >> 5;
    const int lane = tid & 31;
    const bool fast = (d_flagH[0] & d_flagH[1] & d_flagH[2] &
                       d_flagH[3] & d_flagH[4] & d_flagH[5]) != 0;

    if (!fast) {
        for (int idx = tid; idx < kHD * kHD; idx += 256)
            G2sh[(idx >> 7) * PITCH + (idx & 127)] = d_G2[k * kHD * kHD + idx];
    }
    const int tb = k * kBT + b * kT;
    const int seqbase = tb * kHD;
    if (tid < 128) {
        g1sh[tid]  = d_g1[k * kHD + tid];
        v2sh[tid]  = d_v2[k * kHD + tid];
        vbssh[tid] = d_vbs[k * kHD + tid];
        zsh[2 * 128 + tid] = 0.f;      // prev buffer at t=0 (dy=0 -> no-op, keep NaN-free)
        zsh[tid]  = d_Z[seqbase + tid];
        Psh[tid]  = d_P[seqbase + tid];
        if (tid == 0) sxs[0] = d_SX[tb];
    }
    const float S2v  = d_S2[k];
    const float SBSv = d_SBS[k];

    // W: column j, rows half*64..+63 (32 f32x2). G: row j, cols half*64..+63.
    ull W2[32], Gr[32];
    {
        const float* wsrc = W0 + (size_t)k * kHD * kHD;
        #pragma unroll
        for (int p = 0; p < 32; p++) {
            int r0 = half * 64 + 2 * p;
            W2[p] = pack2(wsrc[(size_t)r0 * kHD + j], wsrc[(size_t)(r0 + 1) * kHD + j]);
        }
        const ulonglong2* grow = (const ulonglong2*)(Gsrc + (size_t)(k * kHD + j) * kHD + half * 64);
        #pragma unroll
        for (int p = 0; p < 16; p++) {
            ulonglong2 v = grow[p];
            Gr[2 * p] = v.x; Gr[2 * p + 1] = v.y;
        }
    }
    __syncthreads();

    const float cc = (float)kNH / (float)kD;
    const float invD = 1.f / (float)kD;
    int prevb = 2, curb = 0, nextb = 1;
    float dyO = 0.f;   // register-carried dy[j] from previous step

    for (int t = 0; t < kT; ++t) {
        const int cur2 = t & 1;
        const int nb2 = cur2 ^ 1;
        const ull dyn2 = pack2(-dyO, -dyO);

        // prefetch next token into registers (stashed at top of stage B)
        float nz = 0.f, nP = 0.f, nsx = 0.f;
        if (t + 1 < kT) {
            int pb = seqbase + (t + 1) * kHD;
            if (tid < 128) {
                nz = d_Z[pb + tid];
                nP = d_P[pb + tid];
                if (tid == 0) nsx = d_SX[tb + t + 1];
            }
        }

        // ---- Stage A: W -= z_{t-1} dy^T ; y = z_t @ W ----
        float ypart;
        {
            const ulonglong2* zo2 = (const ulonglong2*)(zsh + prevb * 128 + half * 64);
            const ulonglong2* zc2 = (const ulonglong2*)(zsh + curb * 128 + half * 64);
            ull ya0 = 0ULL, ya1 = 0ULL, ya2 = 0ULL, ya3 = 0ULL;
            #pragma unroll
            for (int p = 0; p < 16; p += 2) {
                ulonglong2 a0 = zo2[p], c0 = zc2[p];
                ulonglong2 a1 = zo2[p + 1], c1 = zc2[p + 1];
                ull w0 = fma2(a0.x, dyn2, W2[2 * p]);
                ull w1 = fma2(a0.y, dyn2, W2[2 * p + 1]);
                ull w2 = fma2(a1.x, dyn2, W2[2 * p + 2]);
                ull w3 = fma2(a1.y, dyn2, W2[2 * p + 3]);
                W2[2 * p] = w0; W2[2 * p + 1] = w1;
                W2[2 * p + 2] = w2; W2[2 * p + 3] = w3;
                ya0 = fma2(c0.x, w0, ya0);
                ya1 = fma2(c0.y, w1, ya1);
                ya2 = fma2(c1.x, w2, ya2);
                ya3 = fma2(c1.y, w3, ya3);
            }
            ypart = hsum2(ya0) + hsum2(ya1) + hsum2(ya2) + hsum2(ya3);
            ypart += __shfl_xor_sync(0xFFFFFFFFu, ypart, 1);
            if (half == 0) ysh[j] = ypart;
        }
        __syncthreads();   // S1: y ready

        // ---- Stage B: stash prefetch, Gy (+G2y), su2/q2 partials, 4 dots ----
        float gpart, g2part;
        {
            // stash (buffers first read after NEXT step's S1 -> race-free)
            if (t + 1 < kT && tid < 128) {
                zsh[nextb * 128 + tid] = nz;
                Psh[nb2 * 128 + tid] = nP;
                if (tid == 0) sxs[nb2] = nsx;
            }

            const ulonglong2* y2 = (const ulonglong2*)(ysh + half * 64);
            ull ga0 = 0ULL, ga1 = 0ULL, ga2 = 0ULL, ga3 = 0ULL;
            #pragma unroll
            for (int p = 0; p < 16; p += 2) {
                ulonglong2 y0 = y2[p], y1 = y2[p + 1];
                ga0 = fma2(Gr[2 * p], y0.x, ga0);
                ga1 = fma2(Gr[2 * p + 1], y0.y, ga1);
                ga2 = fma2(Gr[2 * p + 2], y1.x, ga2);
                ga3 = fma2(Gr[2 * p + 3], y1.y, ga3);
            }
            gpart = hsum2(ga0) + hsum2(ga1) + hsum2(ga2) + hsum2(ga3);
            gpart += __shfl_xor_sync(0xFFFFFFFFu, gpart, 1);
            g2part = gpart;
            if (!fast) {
                const ulonglong2* g2r = (const ulonglong2*)(G2sh + j * PITCH + half * 64);
                ull h0 = 0ULL, h1 = 0ULL, h2 = 0ULL, h3 = 0ULL;
                #pragma unroll
                for (int p = 0; p < 16; p += 2) {
                    ulonglong2 gv0 = g2r[p], gv1 = g2r[p + 1];
                    ulonglong2 y0 = y2[p], y1 = y2[p + 1];
                    h0 = fma2(gv0.x, y0.x, h0);
                    h1 = fma2(gv0.y, y0.y, h1);
                    h2 = fma2(gv1.x, y1.x, h2);
                    h3 = fma2(gv1.y, y1.y, h3);
                }
                g2part = hsum2(h0) + hsum2(h1) + hsum2(h2) + hsum2(h3);
                g2part += __shfl_xor_sync(0xFFFFFFFFu, g2part, 1);
            }

            // su2 / q2 warp partials (only half==0 lanes contribute)
            float yv0 = (half == 0) ? ypart : 0.f;
            float su2p = warpsum(gpart * yv0);
            if (lane == 0) wsumA[wid] = su2p;
            if (!fast) {
                float q2p = warpsum(g2part * yv0);
                if (lane == 0) wsumB[wid] = q2p;
            }

            // 4 dots over 8 warps: which = wid>>1, seg = wid&1 (64 elems, 2/lane)
            {
                const int which = wid >> 1;
                const int e = (wid & 1) * 64 + lane * 2;
                const float* vsel = (which == 0) ? g1sh
                                  : (which == 1) ? (Psh + cur2 * 128)
                                  : (which == 2) ? v2sh : vbssh;
                float2 yv = *(const float2*)&ysh[e];
                float2 vv = *(const float2*)&vsel[e];
                float v = warpsum(fmaf(vv.x, yv.x, vv.y * yv.y));
                if (lane == 0) dparts[wid] = v;
            }
        }
        __syncthreads();   // S2: partials ready

        // ---- Stage E: all threads redundantly compute scalars + their column's dy ----
        {
            const float g1y  = dparts[0] + dparts[1];
            const float Pty  = dparts[2] + dparts[3];
            const float v2y  = dparts[4] + dparts[5];
            const float vbsy = dparts[6] + dparts[7];
            float su2 = (wsumA[0] + wsumA[1]) + (wsumA[2] + wsumA[3])
                      + (wsumA[4] + wsumA[5]) + (wsumA[6] + wsumA[7]);
            float q2 = su2;
            if (!fast)
                q2 = (wsumB[0] + wsumB[1]) + (wsumB[2] + wsumB[3])
                   + (wsumB[4] + wsumB[5]) + (wsumB[6] + wsumB[7]);
            const float SXt = sxs[cur2];

            const float mu = g1y * invD;
            const float var = su2 * invD - mu * mu;
            const float rr = rsqrtf(var + kEPS);
            const float r2 = rr * rr;
            const float mdn  = (cc * invD) * (rr * (v2y - mu * S2v) + SBSv - SXt);
            const float mdnn = (cc * invD) * (r2 * (q2 - 2.f * mu * v2y + mu * mu * S2v)
                                              + rr * (vbsy - mu * SBSv)
                                              - rr * (Pty - mu * SXt));
            const float a1 = cc * r2;
            const float a2 = -r2 * mdnn;
            const float a3 = -cc * rr;
            const float a4 = -cc * r2 * mu;
            const float a5 = cc * rr;
            const float a6 = rr * (mdnn * rr * mu - mdn);
            const float g2y = fast ? gpart : g2part;
            float dyv = a1 * g2y + a2 * gpart + a3 * Psh[cur2 * 128 + j]
                      + a4 * v2sh[j] + a5 * vbssh[j] + a6 * g1sh[j];
            dyO = dyv;   // register-carried to next step (no barrier needed)
            if (half == 0) d_DY[seqbase + t * kHD + j] = dyv;
        }

        int tmp = prevb; prevb = curb; curb = nextb; nextb = tmp;
    }
}

// ---------------- CP_c = Z_c^T @ DY_c ; grid (kNC, 12) ----------------
__global__ void __launch_bounds__(256) chunkA_kernel() {
    const int c = blockIdx.x;
    const int kb = blockIdx.y;
    const int base = (kb >> 1) * kBT + (kb & 1) * kT + c * kC;
    __shared__ float As[16 * GP];
    __shared__ float Bs[16 * GP];
    const int tid = threadIdx.x;
    const int tx = tid & 15, ty = tid >> 4;
    float acc[8][8];
    #pragma unroll
    for (int r = 0; r < 8; r++)
        #pragma unroll
        for (int q = 0; q < 8; q++) acc[r][q] = 0.f;

    for (int r0 = 0; r0 < kC; r0 += 16) {
        int f = tid;
        #pragma unroll
        for (int it = 0; it < 2; it++, f += 256) {
            int kk = f >> 5, c4 = f & 31;
            *(float4*)&As[kk * GP + c4 * 4] =
                *(const float4*)&d_Z[(size_t)(base + r0 + kk) * kHD + c4 * 4];
            *(float4*)&Bs[kk * GP + c4 * 4] =
                *(const float4*)&d_DY[(size_t)(base + r0 + kk) * kHD + c4 * 4];
        }
        __syncthreads();
        #pragma unroll
        for (int kk = 0; kk < 16; kk++) {
            float a[8], bb[8];
            *(float4*)&a[0]  = *(const float4*)&As[kk * GP + ty * 8];
            *(float4*)&a[4]  = *(const float4*)&As[kk * GP + ty * 8 + 4];
            *(float4*)&bb[0] = *(const float4*)&Bs[kk * GP + tx * 8];
            *(float4*)&bb[4] = *(const float4*)&Bs[kk * GP + tx * 8 + 4];
            #pragma unroll
            for (int r = 0; r < 8; r++)
                #pragma unroll
                for (int q = 0; q < 8; q++) acc[r][q] = fmaf(a[r], bb[q], acc[r][q]);
        }
        __syncthreads();
    }
    float* dst = d_CP + (size_t)(kb * kNC + c) * kHD * kHD;
    #pragma unroll
    for (int r = 0; r < 8; r++) {
        int i = ty * 8 + r;
        *(float4*)&dst[(size_t)i * kHD + tx * 8]     = make_float4(acc[r][0], acc[r][1], acc[r][2], acc[r][3]);
        *(float4*)&dst[(size_t)i * kHD + tx * 8 + 4] = make_float4(acc[r][4], acc[r][5], acc[r][6], acc[r][7]);
    }
}

// ---------------- W_c prefix ; grid (12) ----------------
__global__ void __launch_bounds__(256) prefix_kernel(const float* __restrict__ W0) {
    const int kb = blockIdx.x;
    const int k = kb >> 1;
    const int tid = threadIdx.x;
    float w[64];
    #pragma unroll
    for (int e = 0; e < 64; e++) w[e] = W0[(size_t)k * kHD * kHD + e * 256 + tid];
    for (int c = 0; c < kNC; c++) {
        float* dst = d_Wc + (size_t)(kb * kNC + c) * kHD * kHD;
        #pragma unroll
        for (int e = 0; e < 64; e++) dst[e * 256 + tid] = w[e];
        if (c < kNC - 1) {
            const float* cp = d_CP + (size_t)(kb * kNC + c) * kHD * kHD;
            #pragma unroll
            for (int e = 0; e < 64; e++) w[e] -= cp[e * 256 + tid];
        }
    }
}

// ---------------- Q_c = Zpsi_c@W_c - tril(Zpsi_c Z_c^T)@DY_c ; grid (kNC, 12) ----------------
constexpr int QR_SMEM_FLOATS = 128 * PITCH + 2 * 16 * GP;
constexpr int QR_SMEM_BYTES = QR_SMEM_FLOATS * 4;

__global__ void __launch_bounds__(256) qrecon_kernel() {
    const int c = blockIdx.x;
    const int kb = blockIdx.y;
    const int base = (kb >> 1) * kBT + (kb & 1) * kT + c * kC;
    extern __shared__ float qs[];
    float* Msh = qs;                 // tril(S) stored transposed: Msh[r*PITCH + t]
    float* As  = Msh + 128 * PITCH;
    float* Bs  = As + 16 * GP;
    const int tid = threadIdx.x;
    const int tx = tid & 15, ty = tid >> 4;
    const int m = tid >> 2, kq = tid & 3;

    float acc[8][8];
    #pragma unroll
    for (int r = 0; r < 8; r++)
        #pragma unroll
        for (int q = 0; q < 8; q++) acc[r][q] = 0.f;

    // ---- Phase 1: S = Zpsi_c @ Z_c^T ----
    for (int d0 = 0; d0 < kHD; d0 += 16) {
        #pragma unroll
        for (int h2 = 0; h2 < 2; h2++) {
            int mm = m + h2 * 64;
            float4 va = *(const float4*)&d_ZPSI[(size_t)(base + mm) * kHD + d0 + kq * 4];
            As[(kq * 4 + 0) * GP + mm] = va.x;
            As[(kq * 4 + 1) * GP + mm] = va.y;
            As[(kq * 4 + 2) * GP + mm] = va.z;
            As[(kq * 4 + 3) * GP + mm] = va.w;
            float4 vb = *(const float4*)&d_Z[(size_t)(base + mm) * kHD + d0 + kq * 4];
            Bs[(kq * 4 + 0) * GP + mm] = vb.x;
            Bs[(kq * 4 + 1) * GP + mm] = vb.y;
            Bs[(kq * 4 + 2) * GP + mm] = vb.z;
            Bs[(kq * 4 + 3) * GP + mm] = vb.w;
        }
        __syncthreads();
        #pragma unroll
        for (int kk = 0; kk < 16; kk++) {
            float a[8], bb[8];
            *(float4*)&a[0]  = *(const float4*)&As[kk * GP + ty * 8];
            *(float4*)&a[4]  = *(const float4*)&As[kk * GP + ty * 8 + 4];
            *(float4*)&bb[0] = *(const float4*)&Bs[kk * GP + tx * 8];
            *(float4*)&bb[4] = *(const float4*)&Bs[kk * GP + tx * 8 + 4];
            #pragma unroll
            for (int r = 0; r < 8; r++)
                #pragma unroll
                for (int q = 0; q < 8; q++) acc[r][q] = fmaf(a[r], bb[q], acc[r][q]);
        }
        __syncthreads();
    }
    // masked transposed store: Msh[r][t] = (r <= t) ? S[t][r] : 0
    #pragma unroll
    for (int r = 0; r < 8; r++) {
        int t = ty * 8 + r;
        #pragma unroll
        for (int q = 0; q < 8; q++) {
            int rr = tx * 8 + q;
            Msh[rr * PITCH + t] = (rr <= t) ? acc[r][q] : 0.f;
        }
    }
    #pragma unroll
    for (int r = 0; r < 8; r++)
        #pragma unroll
        for (int q = 0; q < 8; q++) acc[r][q] = 0.f;
    __syncthreads();

    // ---- Phase 2: acc = Zpsi_c @ W_c ----
    const float* Wc = d_Wc + (size_t)(kb * kNC + c) * kHD * kHD;
    for (int d0 = 0; d0 < kHD; d0 += 16) {
        #pragma unroll
        for (int h2 = 0; h2 < 2; h2++) {
            int mm = m + h2 * 64;
            float4 va = *(const float4*)&d_ZPSI[(size_t)(base + mm) * kHD + d0 + kq * 4];
            As[(kq * 4 + 0) * GP + mm] = va.x;
            As[(kq * 4 + 1) * GP + mm] = va.y;
            As[(kq * 4 + 2) * GP + mm] = va.z;
            As[(kq * 4 + 3) * GP + mm] = va.w;
        }
        {
            int f = tid;
            #pragma unroll
            for (int it = 0; it < 2; it++, f += 256) {
                int kk = f >> 5, c4 = f & 31;
                *(float4*)&Bs[kk * GP + c4 * 4] =
                    *(const float4*)&Wc[(size_t)(d0 + kk) * kHD + c4 * 4];
            }
        }
        __syncthreads();
        #pragma unroll
        for (int kk = 0; kk < 16; kk++) {
            float a[8], bb[8];
            *(float4*)&a[0]  = *(const float4*)&As[kk * GP + ty * 8];
            *(float4*)&a[4]  = *(const float4*)&As[kk * GP + ty * 8 + 4];
            *(float4*)&bb[0] = *(const float4*)&Bs[kk * GP + tx * 8];
            *(float4*)&bb[4] = *(const float4*)&Bs[kk * GP + tx * 8 + 4];
            #pragma unroll
            for (int r = 0; r < 8; r++)
                #pragma unroll
                for (int q = 0; q < 8; q++) acc[r][q] = fmaf(a[r], bb[q], acc[r][q]);
        }
        __syncthreads();
    }

    // ---- Phase 3: acc -= tril(S) @ DY_c ----
    for (int r0 = 0; r0 < kC; r0 += 16) {
        int f = tid;
        #pragma unroll
        for (int it = 0; it < 2; it++, f += 256) {
            int kk = f >> 5, c4 = f & 31;
            *(float4*)&Bs[kk * GP + c4 * 4] =
                *(const float4*)&d_DY[(size_t)(base + r0 + kk) * kHD + c4 * 4];
        }
        __syncthreads();
        #pragma unroll
        for (int kk = 0; kk < 16; kk++) {
            float a[8], bb[8];
            *(float4*)&a[0]  = *(const float4*)&Msh[(r0 + kk) * PITCH + ty * 8];
            *(float4*)&a[4]  = *(const float4*)&Msh[(r0 + kk) * PITCH + ty * 8 + 4];
            *(float4*)&bb[0] = *(const float4*)&Bs[kk * GP + tx * 8];
            *(float4*)&bb[4] = *(const float4*)&Bs[kk * GP + tx * 8 + 4];
            #pragma unroll
            for (int r = 0; r < 8; r++)
                #pragma unroll
                for (int q = 0; q < 8; q++) acc[r][q] = fmaf(-a[r], bb[q], acc[r][q]);
        }
        __syncthreads();
    }

    #pragma unroll
    for (int r = 0; r < 8; r++) {
        int t = base + ty * 8 + r;
        *(float4*)&d_Q[(size_t)t * kHD + tx * 8]     = make_float4(acc[r][0], acc[r][1], acc[r][2], acc[r][3]);
        *(float4*)&d_Q[(size_t)t * kHD + tx * 8 + 4] = make_float4(acc[r][4], acc[r][5], acc[r][6], acc[r][7]);
    }
}

// ---------------- output GEMM ----------------
__global__ void __launch_bounds__(256) gemm_out_kernel(const float* __restrict__ h,
                                                       float* __restrict__ out) {
    const int n0 = blockIdx.x * 128;
    const int m0 = blockIdx.y * 128;
    __shared__ float As[16 * GP];
    __shared__ float Bs[16 * GP];
    const int tid = threadIdx.x;
    const int tx = tid & 15, ty = tid >> 4;
    ull acc2[8][4];
    #pragma unroll
    for (int r = 0; r < 8; r++)
        #pragma unroll
        for (int c = 0; c < 4; c++) acc2[r][c] = 0ULL;

    for (int k0 = 0; k0 < kNH * kHD; k0 += 16) {
        const int head = k0 >> 7;
        const int j0 = k0 & 127;
        const float* Aq = d_Q + (size_t)head * kBT * kHD;
        {
            int m = tid >> 2, kq = tid & 3;
            #pragma unroll
            for (int h2 = 0; h2 < 2; h2++) {
                int mm = m + h2 * 64;
                float4 v = *(const float4*)&Aq[(size_t)(m0 + mm) * kHD + j0 + kq * 4];
                As[(kq * 4 + 0) * GP + mm] = v.x;
                As[(kq * 4 + 1) * GP + mm] = v.y;
                As[(kq * 4 + 2) * GP + mm] = v.z;
                As[(kq * 4 + 3) * GP + mm] = v.w;
            }
        }
        {
            int f = tid;
            #pragma unroll
            for (int it = 0; it < 2; it++, f += 256) {
                int kk = f >> 5, n4 = f & 31;
                float4 v = *(const float4*)&h[(size_t)(k0 + kk) * kD + n0 + n4 * 4];
                *(float4*)&Bs[kk * GP + n4 * 4] = v;
            }
        }
        __syncthreads();
        #pragma unroll
        for (int kk = 0; kk < 16; kk++) {
            float a[8];
            *(float4*)&a[0]  = *(const float4*)&As[kk * GP + ty * 8];
            *(float4*)&a[4]  = *(const float4*)&As[kk * GP + ty * 8 + 4];
            ulonglong2 b0 = *(const ulonglong2*)&Bs[kk * GP + tx * 8];
            ulonglong2 b1 = *(const ulonglong2*)&Bs[kk * GP + tx * 8 + 4];
            #pragma unroll
            for (int r = 0; r < 8; r++) {
                ull a2 = pack2(a[r], a[r]);
                acc2[r][0] = fma2(a2, b0.x, acc2[r][0]);
                acc2[r][1] = fma2(a2, b0.y, acc2[r][1]);
                acc2[r][2] = fma2(a2, b1.x, acc2[r][2]);
                acc2[r][3] = fma2(a2, b1.y, acc2[r][3]);
            }
        }
        __syncthreads();
    }
    #pragma unroll
    for (int r = 0; r < 8; r++) {
        int mm = m0 + ty * 8 + r;
        *(ulonglong2*)&out[(size_t)mm * kD + n0 + tx * 8]     = make_ulonglong2(acc2[r][0], acc2[r][1]);
        *(ulonglong2*)&out[(size_t)mm * kD + n0 + tx * 8 + 4] = make_ulonglong2(acc2[r][2], acc2[r][3]);
    }
}

// ---------------- launch ----------------
extern "C" void kernel_launch(void* const* d_in, const int* in_sizes, int n_in,
                              void* d_out, int out_size) {
    const float* X   = (const float*)d_in[0];
    const float* psi = (const float*)d_in[1];
    const float* phi = (const float*)d_in[2];
    const float* W0  = (const float*)d_in[3];
    const float* g   = (const float*)d_in[4];
    const float* h   = (const float*)d_in[5];
    const float* lns = (const float*)d_in[6];
    const float* lnb = (const float*)d_in[7];
    float* out = (float*)d_out;
    (void)in_sizes; (void)n_in; (void)out_size;

    float* gptr = nullptr;
    cudaGetSymbolAddress((void**)&gptr, d_G);

    cudaFuncSetAttribute(scan_kernel, cudaFuncAttributeMaxDynamicSharedMemorySize, SCAN_SMEM_BYTES);
    cudaFuncSetAttribute(qrecon_kernel, cudaFuncAttributeMaxDynamicSharedMemorySize, QR_SMEM_BYTES);

    prep_kernel<<<dim3(kNH, 9), 256>>>(g, lns, lnb);
    sx_kernel<<<kBT, 192>>>(X, lns);
    gemm_proj_kernel<<<dim3(1, kBT / 128, 3 * kNH), 256>>>(X, phi, psi, g, lns);
    scan_kernel<<<dim3(kNH, kB), 256, SCAN_SMEM_BYTES>>>(W0, gptr);
    chunkA_kernel<<<dim3(kNC, kNH * kB), 256>>>();
    prefix_kernel<<<kNH * kB, 256>>>(W0);
    qrecon_kernel<<<dim3(kNC, kNH * kB), 256, QR_SMEM_BYTES>>>();
    gemm_out_kernel<<<dim3(kD / 128, kBT / 128), 256>>>(h, out);
}

// round 15
// speedup vs baseline: 2.3768x; 1.0594x over previous
#include <cuda_runtime.h>
#include <cuda_bf16.h>

// ---------------- problem constants ----------------
constexpr int kNH = 6;
constexpr int kD  = 768;
constexpr int kHD = 128;
constexpr int kB  = 2;
constexpr int kT  = 2048;
constexpr int kBT = kB * kT;          // 4096
constexpr int kC  = 128;              // chunk size for Q reconstruction
constexpr int kNC = kT / kC;          // 16 chunks per sequence
constexpr float kEPS = 1e-6f;

constexpr int PITCH = 132;
constexpr int GP    = 132;

typedef unsigned long long ull;

// ---------------- device scratch ----------------
__device__ float d_Z    [kNH * kBT * kHD];
__device__ float d_ZPSI [kNH * kBT * kHD];
__device__ float d_P    [kNH * kBT * kHD];
__device__ float d_DY   [kNH * kBT * kHD];
__device__ float d_Q    [kNH * kBT * kHD];
__device__ float d_CP   [kNH * kB * kNC * kHD * kHD];
__device__ float d_Wc   [kNH * kB * kNC * kHD * kHD];
__device__ float d_SX   [kNH * kBT];
__device__ float d_G    [kNH * kHD * kHD];
__device__ float d_G2   [kNH * kHD * kHD];
__device__ float d_g1   [kNH * kHD];
__device__ float d_v2   [kNH * kHD];
__device__ float d_vbs  [kNH * kHD];
__device__ float d_S2   [kNH];
__device__ float d_SBS  [kNH];
__device__ int   d_flagH[kNH];        // per-head fast-path flag (written fresh each run)

// ---------------- f32x2 helpers ----------------
__device__ __forceinline__ ull fma2(ull a, ull b, ull c) {
    ull d;
    asm("fma.rn.f32x2 %0, %1, %2, %3;" : "=l"(d) : "l"(a), "l"(b), "l"(c));
    return d;
}
__device__ __forceinline__ ull pack2(float lo, float hi) {
    ull r;
    asm("mov.b64 %0, {%1, %2};" : "=l"(r) : "f"(lo), "f"(hi));
    return r;
}
__device__ __forceinline__ float hsum2(ull v) {
    float lo, hi;
    asm("mov.b64 {%0, %1}, %2;" : "=f"(lo), "=f"(hi) : "l"(v));
    return lo + hi;
}
__device__ __forceinline__ float warpsum(float v) {
    #pragma unroll
    for (int o = 16; o > 0; o >>= 1) v += __shfl_xor_sync(0xFFFFFFFFu, v, o);
    return v;
}

// ---------------- prep: G/G2 slices (y<8), rowstats+flag (y==8) ----------------
__global__ void __launch_bounds__(256) prep_kernel(const float* __restrict__ g,
                                                   const float* __restrict__ s,
                                                   const float* __restrict__ b) {
    const int k = blockIdx.x;
    const int y = blockIdx.y;
    const int tid = threadIdx.x;

    if (y < 8) {
        __shared__ float gsh[128 * 33];
        __shared__ float wsh[32];
        const int mode = y >> 2;           // 0 -> G, 1 -> G2
        const int rb = (y & 3) * 32;       // output row base
        const int tx = tid & 15, ty = tid >> 4;
        float acc[2][8];
        #pragma unroll
        for (int r = 0; r < 2; r++)
            #pragma unroll
            for (int c = 0; c < 8; c++) acc[r][c] = 0.f;

        for (int d0 = 0; d0 < kD; d0 += 32) {
            for (int f = tid; f < 128 * 32; f += 256) {
                int i = f >> 5, dd = f & 31;
                gsh[i * 33 + dd] = g[(size_t)(k * kHD + i) * kD + d0 + dd];
            }
            if (tid < 32) {
                float sv = s[k * kD + d0 + tid];
                wsh[tid] = mode ? sv * sv : 1.0f;
            }
            __syncthreads();
            #pragma unroll 4
            for (int dd = 0; dd < 32; dd++) {
                float wv = wsh[dd];
                float a0 = gsh[(rb + ty * 2 + 0) * 33 + dd] * wv;
                float a1 = gsh[(rb + ty * 2 + 1) * 33 + dd] * wv;
                float bb[8];
                #pragma unroll
                for (int c = 0; c < 8; c++) bb[c] = gsh[(tx * 8 + c) * 33 + dd];
                #pragma unroll
                for (int c = 0; c < 8; c++) {
                    acc[0][c] = fmaf(a0, bb[c], acc[0][c]);
                    acc[1][c] = fmaf(a1, bb[c], acc[1][c]);
                }
            }
            __syncthreads();
        }
        float* dst = (mode ? d_G2 : d_G) + k * kHD * kHD;
        #pragma unroll
        for (int r = 0; r < 2; r++)
            #pragma unroll
            for (int c = 0; c < 8; c++)
                dst[(rb + ty * 2 + r) * kHD + tx * 8 + c] = acc[r][c];
    } else {
        if (tid < 128) {
            float a1 = 0.f, a2 = 0.f, a3 = 0.f;
            const float* grow = g + (size_t)(k * kHD + tid) * kD;
            const float* srow = s + k * kD;
            const float* brow = b + k * kD;
            for (int d = 0; d < kD; d++) {
                float gv = grow[d], sv = srow[d], bv = brow[d];
                a1 += gv;
                a2 = fmaf(gv, sv * sv, a2);
                a3 = fmaf(gv, bv * sv, a3);
            }
            d_g1[k * kHD + tid]  = a1;
            d_v2[k * kHD + tid]  = a2;
            d_vbs[k * kHD + tid] = a3;
        }
        float s2p = 0.f, sbp = 0.f;
        int ok = 1;
        for (int d = tid; d < kD; d += 256) {
            float sv = s[k * kD + d], bv = b[k * kD + d];
            s2p = fmaf(sv, sv, s2p);
            sbp = fmaf(bv, sv, sbp);
            ok &= (sv == 1.0f) && (bv == 0.0f);
        }
        __shared__ float red[512];
        __shared__ int oksh;
        if (tid == 0) oksh = 1;
        red[tid] = s2p; red[256 + tid] = sbp;
        __syncthreads();
        if (!__all_sync(0xFFFFFFFFu, ok) && (tid & 31) == 0) atomicAnd(&oksh, 0);
        for (int o = 128; o > 0; o >>= 1) {
            if (tid < o) { red[tid] += red[tid + o]; red[256 + tid] += red[256 + tid + o]; }
            __syncthreads();
        }
        if (tid == 0) { d_S2[k] = red[0]; d_SBS[k] = red[256]; d_flagH[k] = oksh; }
    }
}

// ---------------- SX[k][bt] = sum_d X[bt][d]*s[k][d] ----------------
__global__ void sx_kernel(const float* __restrict__ X, const float* __restrict__ s) {
    const int bt = blockIdx.x;
    const int w = threadIdx.x >> 5;
    const int lane = threadIdx.x & 31;
    float acc = 0.f;
    for (int d0 = lane * 4; d0 < kD; d0 += 128) {
        float4 xv = *(const float4*)&X[bt * kD + d0];
        float4 sv = *(const float4*)&s[w * kD + d0];
        acc = fmaf(xv.x, sv.x, acc);
        acc = fmaf(xv.y, sv.y, acc);
        acc = fmaf(xv.z, sv.z, acc);
        acc = fmaf(xv.w, sv.w, acc);
    }
    acc = warpsum(acc);
    if (lane == 0) d_SX[w * kBT + bt] = acc;
}

// ---------------- projection GEMMs ----------------
__global__ void __launch_bounds__(256) gemm_proj_kernel(const float* __restrict__ X,
                                                        const float* __restrict__ phi,
                                                        const float* __restrict__ psi,
                                                        const float* __restrict__ g,
                                                        const float* __restrict__ s) {
    const int which = blockIdx.z % 3;
    const int head  = blockIdx.z / 3;
    const int m0 = blockIdx.y * 128;
    __shared__ float As[16 * GP];
    __shared__ float Bs[16 * GP];
    const int tid = threadIdx.x;
    const int tx = tid & 15, ty = tid >> 4;
    ull acc2[8][4];
    #pragma unroll
    for (int r = 0; r < 8; r++)
        #pragma unroll
        for (int c = 0; c < 4; c++) acc2[r][c] = 0ULL;

    const float* Bsrc = (which == 0) ? phi : psi;

    for (int k0 = 0; k0 < kD; k0 += 16) {
        {
            int m = tid >> 2, kq = tid & 3;
            #pragma unroll
            for (int h2 = 0; h2 < 2; h2++) {
                int mm = m + h2 * 64;
                float4 v = *(const float4*)&X[(size_t)(m0 + mm) * kD + k0 + kq * 4];
                As[(kq * 4 + 0) * GP + mm] = v.x;
                As[(kq * 4 + 1) * GP + mm] = v.y;
                As[(kq * 4 + 2) * GP + mm] = v.z;
                As[(kq * 4 + 3) * GP + mm] = v.w;
            }
        }
        if (which < 2) {
            int f = tid;
            #pragma unroll
            for (int it = 0; it < 2; it++, f += 256) {
                int kk = f >> 5, n4 = f & 31;
                float4 v = *(const float4*)&Bsrc[(size_t)(head * kD + k0 + kk) * kHD + n4 * 4];
                *(float4*)&Bs[kk * GP + n4 * 4] = v;
            }
        } else {
            int f = tid;
            #pragma unroll
            for (int it = 0; it < 2; it++, f += 256) {
                int jj = f >> 2, kq = f & 3;
                float4 gv = *(const float4*)&g[(size_t)(head * kHD + jj) * kD + k0 + kq * 4];
                float4 sv = *(const float4*)&s[head * kD + k0 + kq * 4];
                Bs[(kq * 4 + 0) * GP + jj] = gv.x * sv.x;
                Bs[(kq * 4 + 1) * GP + jj] = gv.y * sv.y;
                Bs[(kq * 4 + 2) * GP + jj] = gv.z * sv.z;
                Bs[(kq * 4 + 3) * GP + jj] = gv.w * sv.w;
            }
        }
        __syncthreads();
        #pragma unroll
        for (int kk = 0; kk < 16; kk++) {
            float a[8];
            *(float4*)&a[0]  = *(const float4*)&As[kk * GP + ty * 8];
            *(float4*)&a[4]  = *(const float4*)&As[kk * GP + ty * 8 + 4];
            ulonglong2 b0 = *(const ulonglong2*)&Bs[kk * GP + tx * 8];
            ulonglong2 b1 = *(const ulonglong2*)&Bs[kk * GP + tx * 8 + 4];
            #pragma unroll
            for (int r = 0; r < 8; r++) {
                ull a2 = pack2(a[r], a[r]);
                acc2[r][0] = fma2(a2, b0.x, acc2[r][0]);
                acc2[r][1] = fma2(a2, b0.y, acc2[r][1]);
                acc2[r][2] = fma2(a2, b1.x, acc2[r][2]);
                acc2[r][3] = fma2(a2, b1.y, acc2[r][3]);
            }
        }
        __syncthreads();
    }
    float* Cdst = ((which == 0) ? d_Z : (which == 1) ? d_ZPSI : d_P) + (size_t)head * kBT * kHD;
    #pragma unroll
    for (int r = 0; r < 8; r++) {
        int m = m0 + ty * 8 + r;
        *(ulonglong2*)&Cdst[(size_t)m * kHD + tx * 8]     = make_ulonglong2(acc2[r][0], acc2[r][1]);
        *(ulonglong2*)&Cdst[(size_t)m * kHD + tx * 8 + 4] = make_ulonglong2(acc2[r][2], acc2[r][3]);
    }
}

// ---------------- scan: one CTA per (head,batch), 256 threads, R10 structure ----------------
// Thread map: j = tid>>1 (column), half = tid&1 (row half, 64 rows).
constexpr int SCAN_SMEM_FLOATS =
    128 * PITCH      // G2sh (generic path only)
    + 3 * 128        // zsh triple buffer
    + 2 * 128        // Psh double buffer
    + 7 * 128        // ysh, Gysh, G2ysh, dysh, g1sh, v2sh, vbssh
    + 8 + 8 + 8 + 8; // dparts, wsumA, wsumB, sxs
constexpr int SCAN_SMEM_BYTES = SCAN_SMEM_FLOATS * 4;

__global__ void __launch_bounds__(256, 1) scan_kernel(const float* __restrict__ W0,
                                                      const float* __restrict__ Gsrc) {
    extern __shared__ float sm[];
    float* G2sh   = sm;
    float* zsh    = G2sh + 128 * PITCH;   // 3 x 128
    float* Psh    = zsh + 384;            // 2 x 128
    float* ysh    = Psh + 256;
    float* Gysh   = ysh + 128;
    float* G2ysh  = Gysh + 128;
    float* dysh   = G2ysh + 128;
    float* g1sh   = dysh + 128;
    float* v2sh   = g1sh + 128;
    float* vbssh  = v2sh + 128;
    float* dparts = vbssh + 128;   // 8
    float* wsumA  = dparts + 8;    // su2 partials (8 warps)
    float* wsumB  = wsumA + 8;     // q2 partials
    float* sxs    = wsumB + 8;     // SX double buffer

    const int k = blockIdx.x;
    const int b = blockIdx.y;
    const int tid = threadIdx.x;
    const int j = tid >> 1;
    const int half = tid & 1;
    const int wid = tid >> 5;
    const int lane = tid & 31;
    const bool fast = (d_flagH[0] & d_flagH[1] & d_flagH[2] &
                       d_flagH[3] & d_flagH[4] & d_flagH[5]) != 0;

    if (!fast) {
        for (int idx = tid; idx < kHD * kHD; idx += 256)
            G2sh[(idx >> 7) * PITCH + (idx & 127)] = d_G2[k * kHD * kHD + idx];
    }
    const int tb = k * kBT + b * kT;
    const int seqbase = tb * kHD;
    if (tid < 128) {
        g1sh[tid]  = d_g1[k * kHD + tid];
        v2sh[tid]  = d_v2[k * kHD + tid];
        vbssh[tid] = d_vbs[k * kHD + tid];
        dysh[tid]  = 0.f;
        zsh[2 * 128 + tid] = 0.f;      // prev buffer at t=0 (dy=0 -> no-op update)
        zsh[tid]  = d_Z[seqbase + tid];
        Psh[tid]  = d_P[seqbase + tid];
        if (tid == 0) sxs[0] = d_SX[tb];
    }
    const float S2v  = d_S2[k];
    const float SBSv = d_SBS[k];

    // W: column j, rows half*64..+63 (32 f32x2). G: row j, cols half*64..+63.
    ull W2[32], Gr[32];
    {
        const float* wsrc = W0 + (size_t)k * kHD * kHD;
        #pragma unroll
        for (int p = 0; p < 32; p++) {
            int r0 = half * 64 + 2 * p;
            W2[p] = pack2(wsrc[(size_t)r0 * kHD + j], wsrc[(size_t)(r0 + 1) * kHD + j]);
        }
        const ulonglong2* grow = (const ulonglong2*)(Gsrc + (size_t)(k * kHD + j) * kHD + half * 64);
        #pragma unroll
        for (int p = 0; p < 16; p++) {
            ulonglong2 v = grow[p];
            Gr[2 * p] = v.x; Gr[2 * p + 1] = v.y;
        }
    }
    __syncthreads();

    const float cc = (float)kNH / (float)kD;
    const float invD = 1.f / (float)kD;
    int prevb = 2, curb = 0, nextb = 1;

    if (fast) {
        // ============ FAST PATH: ln_scale==1, ln_bias==0 ============
        // v2=g1, vbs=0, S2=D, SBS=0 -> 3 reductions/step, short stage E.
        for (int t = 0; t < kT; ++t) {
            const int cur2 = t & 1;
            const int nb2 = cur2 ^ 1;
            const float dyO = dysh[j];
            const ull dyn2 = pack2(-dyO, -dyO);

            float nz = 0.f, nP = 0.f, nsx = 0.f;
            if (t + 1 < kT) {
                int pb = seqbase + (t + 1) * kHD;
                if (tid < 128) {
                    nz = d_Z[pb + tid];
                    nP = d_P[pb + tid];
                    if (tid == 0) nsx = d_SX[tb + t + 1];
                }
            }

            // ---- Stage A: W -= z_{t-1} dy^T ; y = z_t @ W ----
            float ypart;
            {
                const ulonglong2* zo2 = (const ulonglong2*)(zsh + prevb * 128 + half * 64);
                const ulonglong2* zc2 = (const ulonglong2*)(zsh + curb * 128 + half * 64);
                ull ya0 = 0ULL, ya1 = 0ULL, ya2 = 0ULL, ya3 = 0ULL;
                #pragma unroll
                for (int p = 0; p < 16; p += 2) {
                    ulonglong2 a0 = zo2[p], c0 = zc2[p];
                    ulonglong2 a1 = zo2[p + 1], c1 = zc2[p + 1];
                    ull w0 = fma2(a0.x, dyn2, W2[2 * p]);
                    ull w1 = fma2(a0.y, dyn2, W2[2 * p + 1]);
                    ull w2 = fma2(a1.x, dyn2, W2[2 * p + 2]);
                    ull w3 = fma2(a1.y, dyn2, W2[2 * p + 3]);
                    W2[2 * p] = w0; W2[2 * p + 1] = w1;
                    W2[2 * p + 2] = w2; W2[2 * p + 3] = w3;
                    ya0 = fma2(c0.x, w0, ya0);
                    ya1 = fma2(c0.y, w1, ya1);
                    ya2 = fma2(c1.x, w2, ya2);
                    ya3 = fma2(c1.y, w3, ya3);
                }
                ypart = hsum2(ya0) + hsum2(ya1) + hsum2(ya2) + hsum2(ya3);
                ypart += __shfl_xor_sync(0xFFFFFFFFu, ypart, 1);
                if (half == 0) ysh[j] = ypart;
            }
            __syncthreads();   // S1: y ready

            // ---- Stage B: stash, Gy, su2 (pre-combine), 2 dots ----
            {
                if (t + 1 < kT && tid < 128) {
                    zsh[nextb * 128 + tid] = nz;
                    Psh[nb2 * 128 + tid] = nP;
                    if (tid == 0) sxs[nb2] = nsx;
                }

                const ulonglong2* y2 = (const ulonglong2*)(ysh + half * 64);
                ull ga0 = 0ULL, ga1 = 0ULL, ga2 = 0ULL, ga3 = 0ULL;
                #pragma unroll
                for (int p = 0; p < 16; p += 2) {
                    ulonglong2 y0 = y2[p], y1 = y2[p + 1];
                    ga0 = fma2(Gr[2 * p], y0.x, ga0);
                    ga1 = fma2(Gr[2 * p + 1], y0.y, ga1);
                    ga2 = fma2(Gr[2 * p + 2], y1.x, ga2);
                    ga3 = fma2(Gr[2 * p + 3], y1.y, ga3);
                }
                float gpartH = hsum2(ga0) + hsum2(ga1) + hsum2(ga2) + hsum2(ga3);
                // su2 from pre-combine halves: both lanes contribute y_j * (own half of Gy_j)
                float sp = warpsum(ypart * gpartH);
                if (lane == 0) wsumA[wid] = sp;
                // combine halves for Gy_j (hidden under the warpsum above)
                float gpart = gpartH + __shfl_xor_sync(0xFFFFFFFFu, gpartH, 1);
                if (half == 0) Gysh[j] = gpart;

                // 2 dots over 8 warps: warps 0-3 -> g1.y, warps 4-7 -> P.y
                {
                    const int i = (wid & 3) * 32 + lane;
                    const float* vsel = (wid < 4) ? g1sh : (Psh + cur2 * 128);
                    float v = warpsum(vsel[i] * ysh[i]);
                    if (lane == 0) dparts[wid] = v;
                }
            }
            __syncthreads();   // S2

            // ---- Stage E (tid<128): short scalar chain, dy ----
            if (tid < 128) {
                const float g1y = (dparts[0] + dparts[1]) + (dparts[2] + dparts[3]);
                const float Pty = (dparts[4] + dparts[5]) + (dparts[6] + dparts[7]);
                const float su2 = ((wsumA[0] + wsumA[1]) + (wsumA[2] + wsumA[3]))
                                + ((wsumA[4] + wsumA[5]) + (wsumA[6] + wsumA[7]));
                const float SXt = sxs[cur2];

                const float mu = g1y * invD;
                const float var = su2 * invD - mu * mu;
                const float rr = rsqrtf(var + kEPS);
                const float r2 = rr * rr;
                const float mdn  = -(cc * invD) * SXt;
                const float mdnn = (cc * invD) * (r2 * (su2 - mu * g1y)
                                                  - rr * (Pty - mu * SXt));
                const float aG  = cc * r2 - r2 * mdnn;
                const float a3  = -cc * rr;
                const float ag1 = -cc * r2 * mu + rr * (mdnn * rr * mu - mdn);
                const int i = tid;
                float dyv = aG * Gysh[i] + a3 * Psh[cur2 * 128 + i] + ag1 * g1sh[i];
                dysh[i] = dyv;
                d_DY[seqbase + t * kHD + i] = dyv;
            }
            __syncthreads();   // S3

            int tmp = prevb; prevb = curb; curb = nextb; nextb = tmp;
        }
    } else {
        // ============ GENERIC PATH (R10 body verbatim) ============
        for (int t = 0; t < kT; ++t) {
            const int cur2 = t & 1;
            const int nb2 = cur2 ^ 1;
            const float dyO = dysh[j];
            const ull dyn2 = pack2(-dyO, -dyO);

            float nz = 0.f, nP = 0.f, nsx = 0.f;
            if (t + 1 < kT) {
                int pb = seqbase + (t + 1) * kHD;
                if (tid < 128) {
                    nz = d_Z[pb + tid];
                    nP = d_P[pb + tid];
                    if (tid == 0) nsx = d_SX[tb + t + 1];
                }
            }

            // Stage A
            {
                const ulonglong2* zo2 = (const ulonglong2*)(zsh + prevb * 128 + half * 64);
                const ulonglong2* zc2 = (const ulonglong2*)(zsh + curb * 128 + half * 64);
                ull ya0 = 0ULL, ya1 = 0ULL;
                #pragma unroll
                for (int p = 0; p < 16; p++) {
                    ulonglong2 a = zo2[p], zc = zc2[p];
                    ull w0 = fma2(a.x, dyn2, W2[2 * p]);
                    ull w1 = fma2(a.y, dyn2, W2[2 * p + 1]);
                    W2[2 * p] = w0; W2[2 * p + 1] = w1;
                    ya0 = fma2(zc.x, w0, ya0);
                    ya1 = fma2(zc.y, w1, ya1);
                }
                float ypart = hsum2(ya0) + hsum2(ya1);
                ypart += __shfl_xor_sync(0xFFFFFFFFu, ypart, 1);
                if (half == 0) ysh[j] = ypart;

                if (t + 1 < kT && tid < 128) {
                    zsh[nextb * 128 + tid] = nz;
                    Psh[nb2 * 128 + tid] = nP;
                    if (tid == 0) sxs[nb2] = nsx;
                }
                __syncthreads();   // S1

                // Stage B
                const ulonglong2* y2 = (const ulonglong2*)(ysh + half * 64);
                ull ga0 = 0ULL, ga1 = 0ULL;
                #pragma unroll
                for (int p = 0; p < 16; p++) {
                    ulonglong2 yv = y2[p];
                    ga0 = fma2(Gr[2 * p], yv.x, ga0);
                    ga1 = fma2(Gr[2 * p + 1], yv.y, ga1);
                }
                float gpart = hsum2(ga0) + hsum2(ga1);
                gpart += __shfl_xor_sync(0xFFFFFFFFu, gpart, 1);
                float g2part;
                {
                    const ulonglong2* g2r = (const ulonglong2*)(G2sh + j * PITCH + half * 64);
                    ull h0 = 0ULL, h1 = 0ULL;
                    #pragma unroll
                    for (int p = 0; p < 16; p++) {
                        ulonglong2 gv = g2r[p];
                        ulonglong2 yv = y2[p];
                        h0 = fma2(gv.x, yv.x, h0);
                        h1 = fma2(gv.y, yv.y, h1);
                    }
                    g2part = hsum2(h0) + hsum2(h1);
                    g2part += __shfl_xor_sync(0xFFFFFFFFu, g2part, 1);
                }
                if (half == 0) { Gysh[j] = gpart; G2ysh[j] = g2part; }

                float ypartf = ysh[j];
                float yv0 = (half == 0) ? ypartf : 0.f;
                float su2p = warpsum(gpart * yv0);
                if (lane == 0) wsumA[wid] = su2p;
                float q2p = warpsum(g2part * yv0);
                if (lane == 0) wsumB[wid] = q2p;

                // 4 dots over 8 warps
                {
                    const int which = wid >> 1;
                    const int e = (wid & 1) * 64 + lane * 2;
                    const float* vsel = (which == 0) ? g1sh
                                      : (which == 1) ? (Psh + cur2 * 128)
                                      : (which == 2) ? v2sh : vbssh;
                    float2 yv = *(const float2*)&ysh[e];
                    float2 vv = *(const float2*)&vsel[e];
                    float v = warpsum(fmaf(vv.x, yv.x, vv.y * yv.y));
                    if (lane == 0) dparts[wid] = v;
                }
            }
            __syncthreads();   // S2

            // Stage E
            if (tid < 128) {
                const float g1y  = dparts[0] + dparts[1];
                const float Pty  = dparts[2] + dparts[3];
                const float v2y  = dparts[4] + dparts[5];
                const float vbsy = dparts[6] + dparts[7];
                float su2 = (wsumA[0] + wsumA[1]) + (wsumA[2] + wsumA[3])
                          + (wsumA[4] + wsumA[5]) + (wsumA[6] + wsumA[7]);
                float q2 = (wsumB[0] + wsumB[1]) + (wsumB[2] + wsumB[3])
                         + (wsumB[4] + wsumB[5]) + (wsumB[6] + wsumB[7]);
                const float SXt = sxs[cur2];

                const float mu = g1y * invD;
                const float var = su2 * invD - mu * mu;
                const float rr = rsqrtf(var + kEPS);
                const float r2 = rr * rr;
                const float mdn  = (cc * invD) * (rr * (v2y - mu * S2v) + SBSv - SXt);
                const float mdnn = (cc * invD) * (r2 * (q2 - 2.f * mu * v2y + mu * mu * S2v)
                                                  + rr * (vbsy - mu * SBSv)
                                                  - rr * (Pty - mu * SXt));
                const float a1 = cc * r2;
                const float a2 = -r2 * mdnn;
                const float a3 = -cc * rr;
                const float a4 = -cc * r2 * mu;
                const float a5 = cc * rr;
                const float a6 = rr * (mdnn * rr * mu - mdn);
                const int i = tid;
                float dyv = a1 * G2ysh[i] + a2 * Gysh[i] + a3 * Psh[cur2 * 128 + i]
                          + a4 * v2sh[i] + a5 * vbssh[i] + a6 * g1sh[i];
                dysh[i] = dyv;
                d_DY[seqbase + t * kHD + i] = dyv;
            }
            __syncthreads();   // S3

            int tmp = prevb; prevb = curb; curb = nextb; nextb = tmp;
        }
    }
}

// ---------------- CP_c = Z_c^T @ DY_c ; grid (kNC, 12) ----------------
__global__ void __launch_bounds__(256) chunkA_kernel() {
    const int c = blockIdx.x;
    const int kb = blockIdx.y;
    const int base = (kb >> 1) * kBT + (kb & 1) * kT + c * kC;
    __shared__ float As[16 * GP];
    __shared__ float Bs[16 * GP];
    const int tid = threadIdx.x;
    const int tx = tid & 15, ty = tid >> 4;
    float acc[8][8];
    #pragma unroll
    for (int r = 0; r < 8; r++)
        #pragma unroll
        for (int q = 0; q < 8; q++) acc[r][q] = 0.f;

    for (int r0 = 0; r0 < kC; r0 += 16) {
        int f = tid;
        #pragma unroll
        for (int it = 0; it < 2; it++, f += 256) {
            int kk = f >> 5, c4 = f & 31;
            *(float4*)&As[kk * GP + c4 * 4] =
                *(const float4*)&d_Z[(size_t)(base + r0 + kk) * kHD + c4 * 4];
            *(float4*)&Bs[kk * GP + c4 * 4] =
                *(const float4*)&d_DY[(size_t)(base + r0 + kk) * kHD + c4 * 4];
        }
        __syncthreads();
        #pragma unroll
        for (int kk = 0; kk < 16; kk++) {
            float a[8], bb[8];
            *(float4*)&a[0]  = *(const float4*)&As[kk * GP + ty * 8];
            *(float4*)&a[4]  = *(const float4*)&As[kk * GP + ty * 8 + 4];
            *(float4*)&bb[0] = *(const float4*)&Bs[kk * GP + tx * 8];
            *(float4*)&bb[4] = *(const float4*)&Bs[kk * GP + tx * 8 + 4];
            #pragma unroll
            for (int r = 0; r < 8; r++)
                #pragma unroll
                for (int q = 0; q < 8; q++) acc[r][q] = fmaf(a[r], bb[q], acc[r][q]);
        }
        __syncthreads();
    }
    float* dst = d_CP + (size_t)(kb * kNC + c) * kHD * kHD;
    #pragma unroll
    for (int r = 0; r < 8; r++) {
        int i = ty * 8 + r;
        *(float4*)&dst[(size_t)i * kHD + tx * 8]     = make_float4(acc[r][0], acc[r][1], acc[r][2], acc[r][3]);
        *(float4*)&dst[(size_t)i * kHD + tx * 8 + 4] = make_float4(acc[r][4], acc[r][5], acc[r][6], acc[r][7]);
    }
}

// ---------------- W_c prefix ; grid (12) ----------------
__global__ void __launch_bounds__(256) prefix_kernel(const float* __restrict__ W0) {
    const int kb = blockIdx.x;
    const int k = kb >> 1;
    const int tid = threadIdx.x;
    float w[64];
    #pragma unroll
    for (int e = 0; e < 64; e++) w[e] = W0[(size_t)k * kHD * kHD + e * 256 + tid];
    for (int c = 0; c < kNC; c++) {
        float* dst = d_Wc + (size_t)(kb * kNC + c) * kHD * kHD;
        #pragma unroll
        for (int e = 0; e < 64; e++) dst[e * 256 + tid] = w[e];
        if (c < kNC - 1) {
            const float* cp = d_CP + (size_t)(kb * kNC + c) * kHD * kHD;
            #pragma unroll
            for (int e = 0; e < 64; e++) w[e] -= cp[e * 256 + tid];
        }
    }
}

// ---------------- Q_c = Zpsi_c@W_c - tril(Zpsi_c Z_c^T)@DY_c ; grid (kNC, 12) ----------------
constexpr int QR_SMEM_FLOATS = 128 * PITCH + 2 * 16 * GP;
constexpr int QR_SMEM_BYTES = QR_SMEM_FLOATS * 4;

__global__ void __launch_bounds__(256) qrecon_kernel() {
    const int c = blockIdx.x;
    const int kb = blockIdx.y;
    const int base = (kb >> 1) * kBT + (kb & 1) * kT + c * kC;
    extern __shared__ float qs[];
    float* Msh = qs;                 // tril(S) stored transposed: Msh[r*PITCH + t]
    float* As  = Msh + 128 * PITCH;
    float* Bs  = As + 16 * GP;
    const int tid = threadIdx.x;
    const int tx = tid & 15, ty = tid >> 4;
    const int m = tid >> 2, kq = tid & 3;

    float acc[8][8];
    #pragma unroll
    for (int r = 0; r < 8; r++)
        #pragma unroll
        for (int q = 0; q < 8; q++) acc[r][q] = 0.f;

    // ---- Phase 1: S = Zpsi_c @ Z_c^T ----
    for (int d0 = 0; d0 < kHD; d0 += 16) {
        #pragma unroll
        for (int h2 = 0; h2 < 2; h2++) {
            int mm = m + h2 * 64;
            float4 va = *(const float4*)&d_ZPSI[(size_t)(base + mm) * kHD + d0 + kq * 4];
            As[(kq * 4 + 0) * GP + mm] = va.x;
            As[(kq * 4 + 1) * GP + mm] = va.y;
            As[(kq * 4 + 2) * GP + mm] = va.z;
            As[(kq * 4 + 3) * GP + mm] = va.w;
            float4 vb = *(const float4*)&d_Z[(size_t)(base + mm) * kHD + d0 + kq * 4];
            Bs[(kq * 4 + 0) * GP + mm] = vb.x;
            Bs[(kq * 4 + 1) * GP + mm] = vb.y;
            Bs[(kq * 4 + 2) * GP + mm] = vb.z;
            Bs[(kq * 4 + 3) * GP + mm] = vb.w;
        }
        __syncthreads();
        #pragma unroll
        for (int kk = 0; kk < 16; kk++) {
            float a[8], bb[8];
            *(float4*)&a[0]  = *(const float4*)&As[kk * GP + ty * 8];
            *(float4*)&a[4]  = *(const float4*)&As[kk * GP + ty * 8 + 4];
            *(float4*)&bb[0] = *(const float4*)&Bs[kk * GP + tx * 8];
            *(float4*)&bb[4] = *(const float4*)&Bs[kk * GP + tx * 8 + 4];
            #pragma unroll
            for (int r = 0; r < 8; r++)
                #pragma unroll
                for (int q = 0; q < 8; q++) acc[r][q] = fmaf(a[r], bb[q], acc[r][q]);
        }
        __syncthreads();
    }
    // masked transposed store: Msh[r][t] = (r <= t) ? S[t][r] : 0
    #pragma unroll
    for (int r = 0; r < 8; r++) {
        int t = ty * 8 + r;
        #pragma unroll
        for (int q = 0; q < 8; q++) {
            int rr = tx * 8 + q;
            Msh[rr * PITCH + t] = (rr <= t) ? acc[r][q] : 0.f;
        }
    }
    #pragma unroll
    for (int r = 0; r < 8; r++)
        #pragma unroll
        for (int q = 0; q < 8; q++) acc[r][q] = 0.f;
    __syncthreads();

    // ---- Phase 2: acc = Zpsi_c @ W_c ----
    const float* Wc = d_Wc + (size_t)(kb * kNC + c) * kHD * kHD;
    for (int d0 = 0; d0 < kHD; d0 += 16) {
        #pragma unroll
        for (int h2 = 0; h2 < 2; h2++) {
            int mm = m + h2 * 64;
            float4 va = *(const float4*)&d_ZPSI[(size_t)(base + mm) * kHD + d0 + kq * 4];
            As[(kq * 4 + 0) * GP + mm] = va.x;
            As[(kq * 4 + 1) * GP + mm] = va.y;
            As[(kq * 4 + 2) * GP + mm] = va.z;
            As[(kq * 4 + 3) * GP + mm] = va.w;
        }
        {
            int f = tid;
            #pragma unroll
            for (int it = 0; it < 2; it++, f += 256) {
                int kk = f >> 5, c4 = f & 31;
                *(float4*)&Bs[kk * GP + c4 * 4] =
                    *(const float4*)&Wc[(size_t)(d0 + kk) * kHD + c4 * 4];
            }
        }
        __syncthreads();
        #pragma unroll
        for (int kk = 0; kk < 16; kk++) {
            float a[8], bb[8];
            *(float4*)&a[0]  = *(const float4*)&As[kk * GP + ty * 8];
            *(float4*)&a[4]  = *(const float4*)&As[kk * GP + ty * 8 + 4];
            *(float4*)&bb[0] = *(const float4*)&Bs[kk * GP + tx * 8];
            *(float4*)&bb[4] = *(const float4*)&Bs[kk * GP + tx * 8 + 4];
            #pragma unroll
            for (int r = 0; r < 8; r++)
                #pragma unroll
                for (int q = 0; q < 8; q++) acc[r][q] = fmaf(a[r], bb[q], acc[r][q]);
        }
        __syncthreads();
    }

    // ---- Phase 3: acc -= tril(S) @ DY_c ----
    for (int r0 = 0; r0 < kC; r0 += 16) {
        int f = tid;
        #pragma unroll
        for (int it = 0; it < 2; it++, f += 256) {
            int kk = f >> 5, c4 = f & 31;
            *(float4*)&Bs[kk * GP + c4 * 4] =
                *(const float4*)&d_DY[(size_t)(base + r0 + kk) * kHD + c4 * 4];
        }
        __syncthreads();
        #pragma unroll
        for (int kk = 0; kk < 16; kk++) {
            float a[8], bb[8];
            *(float4*)&a[0]  = *(const float4*)&Msh[(r0 + kk) * PITCH + ty * 8];
            *(float4*)&a[4]  = *(const float4*)&Msh[(r0 + kk) * PITCH + ty * 8 + 4];
            *(float4*)&bb[0] = *(const float4*)&Bs[kk * GP + tx * 8];
            *(float4*)&bb[4] = *(const float4*)&Bs[kk * GP + tx * 8 + 4];
            #pragma unroll
            for (int r = 0; r < 8; r++)
                #pragma unroll
                for (int q = 0; q < 8; q++) acc[r][q] = fmaf(-a[r], bb[q], acc[r][q]);
        }
        __syncthreads();
    }

    #pragma unroll
    for (int r = 0; r < 8; r++) {
        int t = base + ty * 8 + r;
        *(float4*)&d_Q[(size_t)t * kHD + tx * 8]     = make_float4(acc[r][0], acc[r][1], acc[r][2], acc[r][3]);
        *(float4*)&d_Q[(size_t)t * kHD + tx * 8 + 4] = make_float4(acc[r][4], acc[r][5], acc[r][6], acc[r][7]);
    }
}

// ---------------- output GEMM ----------------
__global__ void __launch_bounds__(256) gemm_out_kernel(const float* __restrict__ h,
                                                       float* __restrict__ out) {
    const int n0 = blockIdx.x * 128;
    const int m0 = blockIdx.y * 128;
    __shared__ float As[16 * GP];
    __shared__ float Bs[16 * GP];
    const int tid = threadIdx.x;
    const int tx = tid & 15, ty = tid >> 4;
    ull acc2[8][4];
    #pragma unroll
    for (int r = 0; r < 8; r++)
        #pragma unroll
        for (int c = 0; c < 4; c++) acc2[r][c] = 0ULL;

    for (int k0 = 0; k0 < kNH * kHD; k0 += 16) {
        const int head = k0 >> 7;
        const int j0 = k0 & 127;
        const float* Aq = d_Q + (size_t)head * kBT * kHD;
        {
            int m = tid >> 2, kq = tid & 3;
            #pragma unroll
            for (int h2 = 0; h2 < 2; h2++) {
                int mm = m + h2 * 64;
                float4 v = *(const float4*)&Aq[(size_t)(m0 + mm) * kHD + j0 + kq * 4];
                As[(kq * 4 + 0) * GP + mm] = v.x;
                As[(kq * 4 + 1) * GP + mm] = v.y;
                As[(kq * 4 + 2) * GP + mm] = v.z;
                As[(kq * 4 + 3) * GP + mm] = v.w;
            }
        }
        {
            int f = tid;
            #pragma unroll
            for (int it = 0; it < 2; it++, f += 256) {
                int kk = f >> 5, n4 = f & 31;
                float4 v = *(const float4*)&h[(size_t)(k0 + kk) * kD + n0 + n4 * 4];
                *(float4*)&Bs[kk * GP + n4 * 4] = v;
            }
        }
        __syncthreads();
        #pragma unroll
        for (int kk = 0; kk < 16; kk++) {
            float a[8];
            *(float4*)&a[0]  = *(const float4*)&As[kk * GP + ty * 8];
            *(float4*)&a[4]  = *(const float4*)&As[kk * GP + ty * 8 + 4];
            ulonglong2 b0 = *(const ulonglong2*)&Bs[kk * GP + tx * 8];
            ulonglong2 b1 = *(const ulonglong2*)&Bs[kk * GP + tx * 8 + 4];
            #pragma unroll
            for (int r = 0; r < 8; r++) {
                ull a2 = pack2(a[r], a[r]);
                acc2[r][0] = fma2(a2, b0.x, acc2[r][0]);
                acc2[r][1] = fma2(a2, b0.y, acc2[r][1]);
                acc2[r][2] = fma2(a2, b1.x, acc2[r][2]);
                acc2[r][3] = fma2(a2, b1.y, acc2[r][3]);
            }
        }
        __syncthreads();
    }
    #pragma unroll
    for (int r = 0; r < 8; r++) {
        int mm = m0 + ty * 8 + r;
        *(ulonglong2*)&out[(size_t)mm * kD + n0 + tx * 8]     = make_ulonglong2(acc2[r][0], acc2[r][1]);
        *(ulonglong2*)&out[(size_t)mm * kD + n0 + tx * 8 + 4] = make_ulonglong2(acc2[r][2], acc2[r][3]);
    }
}

// ---------------- launch ----------------
extern "C" void kernel_launch(void* const* d_in, const int* in_sizes, int n_in,
                              void* d_out, int out_size) {
    const float* X   = (const float*)d_in[0];
    const float* psi = (const float*)d_in[1];
    const float* phi = (const float*)d_in[2];
    const float* W0  = (const float*)d_in[3];
    const float* g   = (const float*)d_in[4];
    const float* h   = (const float*)d_in[5];
    const float* lns = (const float*)d_in[6];
    const float* lnb = (const float*)d_in[7];
    float* out = (float*)d_out;
    (void)in_sizes; (void)n_in; (void)out_size;

    float* gptr = nullptr;
    cudaGetSymbolAddress((void**)&gptr, d_G);

    cudaFuncSetAttribute(scan_kernel, cudaFuncAttributeMaxDynamicSharedMemorySize, SCAN_SMEM_BYTES);
    cudaFuncSetAttribute(qrecon_kernel, cudaFuncAttributeMaxDynamicSharedMemorySize, QR_SMEM_BYTES);

    prep_kernel<<<dim3(kNH, 9), 256>>>(g, lns, lnb);
    sx_kernel<<<kBT, 192>>>(X, lns);
    gemm_proj_kernel<<<dim3(1, kBT / 128, 3 * kNH), 256>>>(X, phi, psi, g, lns);
    scan_kernel<<<dim3(kNH, kB), 256, SCAN_SMEM_BYTES>>>(W0, gptr);
    chunkA_kernel<<<dim3(kNC, kNH * kB), 256>>>();
    prefix_kernel<<<kNH * kB, 256>>>(W0);
    qrecon_kernel<<<dim3(kNC, kNH * kB), 256, QR_SMEM_BYTES>>>();
    gemm_out_kernel<<<dim3(kD / 128, kBT / 128), 256>>>(h, out);
}

// round 16
// speedup vs baseline: 2.4000x; 1.0098x over previous
#include <cuda_runtime.h>
#include <cuda_bf16.h>

// ---------------- problem constants ----------------
constexpr int kNH = 6;
constexpr int kD  = 768;
constexpr int kHD = 128;
constexpr int kB  = 2;
constexpr int kT  = 2048;
constexpr int kBT = kB * kT;          // 4096
constexpr int kC  = 128;              // chunk size for Q reconstruction
constexpr int kNC = kT / kC;          // 16 chunks per sequence
constexpr float kEPS = 1e-6f;

constexpr int PITCH = 132;
constexpr int GP    = 132;

typedef unsigned long long ull;

// ---------------- device scratch ----------------
__device__ float d_Z    [kNH * kBT * kHD];
__device__ float d_ZPSI [kNH * kBT * kHD];
__device__ float d_P    [kNH * kBT * kHD];
__device__ float d_DY   [kNH * kBT * kHD];
__device__ float d_Q    [kNH * kBT * kHD];
__device__ float d_SX   [kNH * kBT];
__device__ float d_G    [kNH * kHD * kHD];
__device__ float d_G2   [kNH * kHD * kHD];
__device__ float d_g1   [kNH * kHD];
__device__ float d_v2   [kNH * kHD];
__device__ float d_vbs  [kNH * kHD];
__device__ float d_S2   [kNH];
__device__ float d_SBS  [kNH];
__device__ int   d_flagH[kNH];        // per-head fast-path flag
__device__ int   d_prog [kNH * kB];   // scan chunk progress per (head,batch)

// ---------------- f32x2 helpers ----------------
__device__ __forceinline__ ull fma2(ull a, ull b, ull c) {
    ull d;
    asm("fma.rn.f32x2 %0, %1, %2, %3;" : "=l"(d) : "l"(a), "l"(b), "l"(c));
    return d;
}
__device__ __forceinline__ ull pack2(float lo, float hi) {
    ull r;
    asm("mov.b64 %0, {%1, %2};" : "=l"(r) : "f"(lo), "f"(hi));
    return r;
}
__device__ __forceinline__ float hsum2(ull v) {
    float lo, hi;
    asm("mov.b64 {%0, %1}, %2;" : "=f"(lo), "=f"(hi) : "l"(v));
    return lo + hi;
}
__device__ __forceinline__ float warpsum(float v) {
    #pragma unroll
    for (int o = 16; o > 0; o >>= 1) v += __shfl_xor_sync(0xFFFFFFFFu, v, o);
    return v;
}

// ---------------- prep: G/G2 slices (y<8), rowstats+flag+prog-reset (y==8) ----------------
__global__ void __launch_bounds__(256) prep_kernel(const float* __restrict__ g,
                                                   const float* __restrict__ s,
                                                   const float* __restrict__ b) {
    const int k = blockIdx.x;
    const int y = blockIdx.y;
    const int tid = threadIdx.x;

    if (y < 8) {
        __shared__ float gsh[128 * 33];
        __shared__ float wsh[32];
        const int mode = y >> 2;           // 0 -> G, 1 -> G2
        const int rb = (y & 3) * 32;       // output row base
        const int tx = tid & 15, ty = tid >> 4;
        float acc[2][8];
        #pragma unroll
        for (int r = 0; r < 2; r++)
            #pragma unroll
            for (int c = 0; c < 8; c++) acc[r][c] = 0.f;

        for (int d0 = 0; d0 < kD; d0 += 32) {
            for (int f = tid; f < 128 * 32; f += 256) {
                int i = f >> 5, dd = f & 31;
                gsh[i * 33 + dd] = g[(size_t)(k * kHD + i) * kD + d0 + dd];
            }
            if (tid < 32) {
                float sv = s[k * kD + d0 + tid];
                wsh[tid] = mode ? sv * sv : 1.0f;
            }
            __syncthreads();
            #pragma unroll 4
            for (int dd = 0; dd < 32; dd++) {
                float wv = wsh[dd];
                float a0 = gsh[(rb + ty * 2 + 0) * 33 + dd] * wv;
                float a1 = gsh[(rb + ty * 2 + 1) * 33 + dd] * wv;
                float bb[8];
                #pragma unroll
                for (int c = 0; c < 8; c++) bb[c] = gsh[(tx * 8 + c) * 33 + dd];
                #pragma unroll
                for (int c = 0; c < 8; c++) {
                    acc[0][c] = fmaf(a0, bb[c], acc[0][c]);
                    acc[1][c] = fmaf(a1, bb[c], acc[1][c]);
                }
            }
            __syncthreads();
        }
        float* dst = (mode ? d_G2 : d_G) + k * kHD * kHD;
        #pragma unroll
        for (int r = 0; r < 2; r++)
            #pragma unroll
            for (int c = 0; c < 8; c++)
                dst[(rb + ty * 2 + r) * kHD + tx * 8 + c] = acc[r][c];
    } else {
        if (tid < 2) d_prog[k * 2 + tid] = 0;   // reset progress (before fused kernel)
        if (tid < 128) {
            float a1 = 0.f, a2 = 0.f, a3 = 0.f;
            const float* grow = g + (size_t)(k * kHD + tid) * kD;
            const float* srow = s + k * kD;
            const float* brow = b + k * kD;
            for (int d = 0; d < kD; d++) {
                float gv = grow[d], sv = srow[d], bv = brow[d];
                a1 += gv;
                a2 = fmaf(gv, sv * sv, a2);
                a3 = fmaf(gv, bv * sv, a3);
            }
            d_g1[k * kHD + tid]  = a1;
            d_v2[k * kHD + tid]  = a2;
            d_vbs[k * kHD + tid] = a3;
        }
        float s2p = 0.f, sbp = 0.f;
        int ok = 1;
        for (int d = tid; d < kD; d += 256) {
            float sv = s[k * kD + d], bv = b[k * kD + d];
            s2p = fmaf(sv, sv, s2p);
            sbp = fmaf(bv, sv, sbp);
            ok &= (sv == 1.0f) && (bv == 0.0f);
        }
        __shared__ float red[512];
        __shared__ int oksh;
        if (tid == 0) oksh = 1;
        red[tid] = s2p; red[256 + tid] = sbp;
        __syncthreads();
        if (!__all_sync(0xFFFFFFFFu, ok) && (tid & 31) == 0) atomicAnd(&oksh, 0);
        for (int o = 128; o > 0; o >>= 1) {
            if (tid < o) { red[tid] += red[tid + o]; red[256 + tid] += red[256 + tid + o]; }
            __syncthreads();
        }
        if (tid == 0) { d_S2[k] = red[0]; d_SBS[k] = red[256]; d_flagH[k] = oksh; }
    }
}

// ---------------- SX[k][bt] = sum_d X[bt][d]*s[k][d] ----------------
__global__ void sx_kernel(const float* __restrict__ X, const float* __restrict__ s) {
    const int bt = blockIdx.x;
    const int w = threadIdx.x >> 5;
    const int lane = threadIdx.x & 31;
    float acc = 0.f;
    for (int d0 = lane * 4; d0 < kD; d0 += 128) {
        float4 xv = *(const float4*)&X[bt * kD + d0];
        float4 sv = *(const float4*)&s[w * kD + d0];
        acc = fmaf(xv.x, sv.x, acc);
        acc = fmaf(xv.y, sv.y, acc);
        acc = fmaf(xv.z, sv.z, acc);
        acc = fmaf(xv.w, sv.w, acc);
    }
    acc = warpsum(acc);
    if (lane == 0) d_SX[w * kBT + bt] = acc;
}

// ---------------- projection GEMMs ----------------
__global__ void __launch_bounds__(256) gemm_proj_kernel(const float* __restrict__ X,
                                                        const float* __restrict__ phi,
                                                        const float* __restrict__ psi,
                                                        const float* __restrict__ g,
                                                        const float* __restrict__ s) {
    const int which = blockIdx.z % 3;
    const int head  = blockIdx.z / 3;
    const int m0 = blockIdx.y * 128;
    __shared__ float As[16 * GP];
    __shared__ float Bs[16 * GP];
    const int tid = threadIdx.x;
    const int tx = tid & 15, ty = tid >> 4;
    ull acc2[8][4];
    #pragma unroll
    for (int r = 0; r < 8; r++)
        #pragma unroll
        for (int c = 0; c < 4; c++) acc2[r][c] = 0ULL;

    const float* Bsrc = (which == 0) ? phi : psi;

    for (int k0 = 0; k0 < kD; k0 += 16) {
        {
            int m = tid >> 2, kq = tid & 3;
            #pragma unroll
            for (int h2 = 0; h2 < 2; h2++) {
                int mm = m + h2 * 64;
                float4 v = *(const float4*)&X[(size_t)(m0 + mm) * kD + k0 + kq * 4];
                As[(kq * 4 + 0) * GP + mm] = v.x;
                As[(kq * 4 + 1) * GP + mm] = v.y;
                As[(kq * 4 + 2) * GP + mm] = v.z;
                As[(kq * 4 + 3) * GP + mm] = v.w;
            }
        }
        if (which < 2) {
            int f = tid;
            #pragma unroll
            for (int it = 0; it < 2; it++, f += 256) {
                int kk = f >> 5, n4 = f & 31;
                float4 v = *(const float4*)&Bsrc[(size_t)(head * kD + k0 + kk) * kHD + n4 * 4];
                *(float4*)&Bs[kk * GP + n4 * 4] = v;
            }
        } else {
            int f = tid;
            #pragma unroll
            for (int it = 0; it < 2; it++, f += 256) {
                int jj = f >> 2, kq = f & 3;
                float4 gv = *(const float4*)&g[(size_t)(head * kHD + jj) * kD + k0 + kq * 4];
                float4 sv = *(const float4*)&s[head * kD + k0 + kq * 4];
                Bs[(kq * 4 + 0) * GP + jj] = gv.x * sv.x;
                Bs[(kq * 4 + 1) * GP + jj] = gv.y * sv.y;
                Bs[(kq * 4 + 2) * GP + jj] = gv.z * sv.z;
                Bs[(kq * 4 + 3) * GP + jj] = gv.w * sv.w;
            }
        }
        __syncthreads();
        #pragma unroll
        for (int kk = 0; kk < 16; kk++) {
            float a[8];
            *(float4*)&a[0]  = *(const float4*)&As[kk * GP + ty * 8];
            *(float4*)&a[4]  = *(const float4*)&As[kk * GP + ty * 8 + 4];
            ulonglong2 b0 = *(const ulonglong2*)&Bs[kk * GP + tx * 8];
            ulonglong2 b1 = *(const ulonglong2*)&Bs[kk * GP + tx * 8 + 4];
            #pragma unroll
            for (int r = 0; r < 8; r++) {
                ull a2 = pack2(a[r], a[r]);
                acc2[r][0] = fma2(a2, b0.x, acc2[r][0]);
                acc2[r][1] = fma2(a2, b0.y, acc2[r][1]);
                acc2[r][2] = fma2(a2, b1.x, acc2[r][2]);
                acc2[r][3] = fma2(a2, b1.y, acc2[r][3]);
            }
        }
        __syncthreads();
    }
    float* Cdst = ((which == 0) ? d_Z : (which == 1) ? d_ZPSI : d_P) + (size_t)head * kBT * kHD;
    #pragma unroll
    for (int r = 0; r < 8; r++) {
        int m = m0 + ty * 8 + r;
        *(ulonglong2*)&Cdst[(size_t)m * kHD + tx * 8]     = make_ulonglong2(acc2[r][0], acc2[r][1]);
        *(ulonglong2*)&Cdst[(size_t)m * kHD + tx * 8 + 4] = make_ulonglong2(acc2[r][2], acc2[r][3]);
    }
}

// ---------------- fused scan + chunked Q reconstruction ----------------
// bid 0-11: scan CTA for (k=bid>>1, b=bid&1); emits DY + progress flags.
// bid 12-23: consumer CTA for kb=bid-12; per chunk polls progress, then
//            Q_c = Zpsi_c@W_c - tril(Zpsi_c Z_c^T)@DY_c ; W_{c+1} = W_c - Z_c^T@DY_c.
constexpr int SCAN_SMEM_FLOATS =
    128 * PITCH + 3 * 128 + 2 * 128 + 7 * 128 + 8 + 8 + 8 + 8;
constexpr int CONS_SMEM_FLOATS = 2 * 128 * PITCH + 2 * 16 * GP;
constexpr int FUSED_SMEM_FLOATS =
    (SCAN_SMEM_FLOATS > CONS_SMEM_FLOATS) ? SCAN_SMEM_FLOATS : CONS_SMEM_FLOATS;
constexpr int FUSED_SMEM_BYTES = FUSED_SMEM_FLOATS * 4;

__global__ void __launch_bounds__(256, 1) fused_kernel(const float* __restrict__ W0,
                                                       const float* __restrict__ Gsrc) {
    extern __shared__ float sm[];
    const int bid = blockIdx.x;
    const int tid = threadIdx.x;

    if (bid < kNH * kB) {
        // ================= SCAN =================
        float* G2sh   = sm;
        float* zsh    = G2sh + 128 * PITCH;   // 3 x 128
        float* Psh    = zsh + 384;            // 2 x 128
        float* ysh    = Psh + 256;
        float* Gysh   = ysh + 128;
        float* G2ysh  = Gysh + 128;
        float* dysh   = G2ysh + 128;
        float* g1sh   = dysh + 128;
        float* v2sh   = g1sh + 128;
        float* vbssh  = v2sh + 128;
        float* dparts = vbssh + 128;
        float* wsumA  = dparts + 8;
        float* wsumB  = wsumA + 8;
        float* sxs    = wsumB + 8;

        const int k = bid >> 1;
        const int b = bid & 1;
        const int j = tid >> 1;
        const int half = tid & 1;
        const int wid = tid >> 5;
        const int lane = tid & 31;
        const bool fast = (d_flagH[0] & d_flagH[1] & d_flagH[2] &
                           d_flagH[3] & d_flagH[4] & d_flagH[5]) != 0;

        if (!fast) {
            for (int idx = tid; idx < kHD * kHD; idx += 256)
                G2sh[(idx >> 7) * PITCH + (idx & 127)] = d_G2[k * kHD * kHD + idx];
        }
        const int tb = k * kBT + b * kT;
        const int seqbase = tb * kHD;
        if (tid < 128) {
            g1sh[tid]  = d_g1[k * kHD + tid];
            v2sh[tid]  = d_v2[k * kHD + tid];
            vbssh[tid] = d_vbs[k * kHD + tid];
            dysh[tid]  = 0.f;
            zsh[2 * 128 + tid] = 0.f;
            zsh[tid]  = d_Z[seqbase + tid];
            Psh[tid]  = d_P[seqbase + tid];
            if (tid == 0) sxs[0] = d_SX[tb];
        }
        const float S2v  = d_S2[k];
        const float SBSv = d_SBS[k];

        ull W2[32], Gr[32];
        {
            const float* wsrc = W0 + (size_t)k * kHD * kHD;
            #pragma unroll
            for (int p = 0; p < 32; p++) {
                int r0 = half * 64 + 2 * p;
                W2[p] = pack2(wsrc[(size_t)r0 * kHD + j], wsrc[(size_t)(r0 + 1) * kHD + j]);
            }
            const ulonglong2* grow = (const ulonglong2*)(Gsrc + (size_t)(k * kHD + j) * kHD + half * 64);
            #pragma unroll
            for (int p = 0; p < 16; p++) {
                ulonglong2 v = grow[p];
                Gr[2 * p] = v.x; Gr[2 * p + 1] = v.y;
            }
        }
        __syncthreads();

        const float cc = (float)kNH / (float)kD;
        const float invD = 1.f / (float)kD;
        int prevb = 2, curb = 0, nextb = 1;

        if (fast) {
            for (int t = 0; t < kT; ++t) {
                const int cur2 = t & 1;
                const int nb2 = cur2 ^ 1;
                const float dyO = dysh[j];
                const ull dyn2 = pack2(-dyO, -dyO);

                float nz = 0.f, nP = 0.f, nsx = 0.f;
                if (t + 1 < kT) {
                    int pb = seqbase + (t + 1) * kHD;
                    if (tid < 128) {
                        nz = d_Z[pb + tid];
                        nP = d_P[pb + tid];
                        if (tid == 0) nsx = d_SX[tb + t + 1];
                    }
                }

                float ypart;
                {
                    const ulonglong2* zo2 = (const ulonglong2*)(zsh + prevb * 128 + half * 64);
                    const ulonglong2* zc2 = (const ulonglong2*)(zsh + curb * 128 + half * 64);
                    ull ya0 = 0ULL, ya1 = 0ULL, ya2 = 0ULL, ya3 = 0ULL;
                    #pragma unroll
                    for (int p = 0; p < 16; p += 2) {
                        ulonglong2 a0 = zo2[p], c0 = zc2[p];
                        ulonglong2 a1 = zo2[p + 1], c1 = zc2[p + 1];
                        ull w0 = fma2(a0.x, dyn2, W2[2 * p]);
                        ull w1 = fma2(a0.y, dyn2, W2[2 * p + 1]);
                        ull w2 = fma2(a1.x, dyn2, W2[2 * p + 2]);
                        ull w3 = fma2(a1.y, dyn2, W2[2 * p + 3]);
                        W2[2 * p] = w0; W2[2 * p + 1] = w1;
                        W2[2 * p + 2] = w2; W2[2 * p + 3] = w3;
                        ya0 = fma2(c0.x, w0, ya0);
                        ya1 = fma2(c0.y, w1, ya1);
                        ya2 = fma2(c1.x, w2, ya2);
                        ya3 = fma2(c1.y, w3, ya3);
                    }
                    ypart = hsum2(ya0) + hsum2(ya1) + hsum2(ya2) + hsum2(ya3);
                    ypart += __shfl_xor_sync(0xFFFFFFFFu, ypart, 1);
                    if (half == 0) ysh[j] = ypart;
                }
                __syncthreads();   // S1

                {
                    if (t + 1 < kT && tid < 128) {
                        zsh[nextb * 128 + tid] = nz;
                        Psh[nb2 * 128 + tid] = nP;
                        if (tid == 0) sxs[nb2] = nsx;
                    }

                    const ulonglong2* y2 = (const ulonglong2*)(ysh + half * 64);
                    ull ga0 = 0ULL, ga1 = 0ULL, ga2 = 0ULL, ga3 = 0ULL;
                    #pragma unroll
                    for (int p = 0; p < 16; p += 2) {
                        ulonglong2 y0 = y2[p], y1 = y2[p + 1];
                        ga0 = fma2(Gr[2 * p], y0.x, ga0);
                        ga1 = fma2(Gr[2 * p + 1], y0.y, ga1);
                        ga2 = fma2(Gr[2 * p + 2], y1.x, ga2);
                        ga3 = fma2(Gr[2 * p + 3], y1.y, ga3);
                    }
                    float gpartH = hsum2(ga0) + hsum2(ga1) + hsum2(ga2) + hsum2(ga3);
                    float sp = warpsum(ypart * gpartH);
                    if (lane == 0) wsumA[wid] = sp;
                    float gpart = gpartH + __shfl_xor_sync(0xFFFFFFFFu, gpartH, 1);
                    if (half == 0) Gysh[j] = gpart;

                    {
                        const int i = (wid & 3) * 32 + lane;
                        const float* vsel = (wid < 4) ? g1sh : (Psh + cur2 * 128);
                        float v = warpsum(vsel[i] * ysh[i]);
                        if (lane == 0) dparts[wid] = v;
                    }
                }
                __syncthreads();   // S2

                if (tid < 128) {
                    const float g1y = (dparts[0] + dparts[1]) + (dparts[2] + dparts[3]);
                    const float Pty = (dparts[4] + dparts[5]) + (dparts[6] + dparts[7]);
                    const float su2 = ((wsumA[0] + wsumA[1]) + (wsumA[2] + wsumA[3]))
                                    + ((wsumA[4] + wsumA[5]) + (wsumA[6] + wsumA[7]));
                    const float SXt = sxs[cur2];

                    const float mu = g1y * invD;
                    const float var = su2 * invD - mu * mu;
                    const float rr = rsqrtf(var + kEPS);
                    const float r2 = rr * rr;
                    const float mdn  = -(cc * invD) * SXt;
                    const float mdnn = (cc * invD) * (r2 * (su2 - mu * g1y)
                                                      - rr * (Pty - mu * SXt));
                    const float aG  = cc * r2 - r2 * mdnn;
                    const float a3  = -cc * rr;
                    const float ag1 = -cc * r2 * mu + rr * (mdnn * rr * mu - mdn);
                    const int i = tid;
                    float dyv = aG * Gysh[i] + a3 * Psh[cur2 * 128 + i] + ag1 * g1sh[i];
                    dysh[i] = dyv;
                    d_DY[seqbase + t * kHD + i] = dyv;
                }
                if ((t & 127) == 127) __threadfence();
                __syncthreads();   // S3
                if ((t & 127) == 127 && tid == 0)
                    atomicExch(&d_prog[bid], (t >> 7) + 1);

                int tmp = prevb; prevb = curb; curb = nextb; nextb = tmp;
            }
        } else {
            for (int t = 0; t < kT; ++t) {
                const int cur2 = t & 1;
                const int nb2 = cur2 ^ 1;
                const float dyO = dysh[j];
                const ull dyn2 = pack2(-dyO, -dyO);

                float nz = 0.f, nP = 0.f, nsx = 0.f;
                if (t + 1 < kT) {
                    int pb = seqbase + (t + 1) * kHD;
                    if (tid < 128) {
                        nz = d_Z[pb + tid];
                        nP = d_P[pb + tid];
                        if (tid == 0) nsx = d_SX[tb + t + 1];
                    }
                }

                {
                    const ulonglong2* zo2 = (const ulonglong2*)(zsh + prevb * 128 + half * 64);
                    const ulonglong2* zc2 = (const ulonglong2*)(zsh + curb * 128 + half * 64);
                    ull ya0 = 0ULL, ya1 = 0ULL;
                    #pragma unroll
                    for (int p = 0; p < 16; p++) {
                        ulonglong2 a = zo2[p], zc = zc2[p];
                        ull w0 = fma2(a.x, dyn2, W2[2 * p]);
                        ull w1 = fma2(a.y, dyn2, W2[2 * p + 1]);
                        W2[2 * p] = w0; W2[2 * p + 1] = w1;
                        ya0 = fma2(zc.x, w0, ya0);
                        ya1 = fma2(zc.y, w1, ya1);
                    }
                    float ypart = hsum2(ya0) + hsum2(ya1);
                    ypart += __shfl_xor_sync(0xFFFFFFFFu, ypart, 1);
                    if (half == 0) ysh[j] = ypart;

                    if (t + 1 < kT && tid < 128) {
                        zsh[nextb * 128 + tid] = nz;
                        Psh[nb2 * 128 + tid] = nP;
                        if (tid == 0) sxs[nb2] = nsx;
                    }
                    __syncthreads();   // S1

                    const ulonglong2* y2 = (const ulonglong2*)(ysh + half * 64);
                    ull ga0 = 0ULL, ga1 = 0ULL;
                    #pragma unroll
                    for (int p = 0; p < 16; p++) {
                        ulonglong2 yv = y2[p];
                        ga0 = fma2(Gr[2 * p], yv.x, ga0);
                        ga1 = fma2(Gr[2 * p + 1], yv.y, ga1);
                    }
                    float gpart = hsum2(ga0) + hsum2(ga1);
                    gpart += __shfl_xor_sync(0xFFFFFFFFu, gpart, 1);
                    float g2part;
                    {
                        const ulonglong2* g2r = (const ulonglong2*)(G2sh + j * PITCH + half * 64);
                        ull h0 = 0ULL, h1 = 0ULL;
                        #pragma unroll
                        for (int p = 0; p < 16; p++) {
                            ulonglong2 gv = g2r[p];
                            ulonglong2 yv = y2[p];
                            h0 = fma2(gv.x, yv.x, h0);
                            h1 = fma2(gv.y, yv.y, h1);
                        }
                        g2part = hsum2(h0) + hsum2(h1);
                        g2part += __shfl_xor_sync(0xFFFFFFFFu, g2part, 1);
                    }
                    if (half == 0) { Gysh[j] = gpart; G2ysh[j] = g2part; }

                    float ypartf = ysh[j];
                    float yv0 = (half == 0) ? ypartf : 0.f;
                    float su2p = warpsum(gpart * yv0);
                    if (lane == 0) wsumA[wid] = su2p;
                    float q2p = warpsum(g2part * yv0);
                    if (lane == 0) wsumB[wid] = q2p;

                    {
                        const int which = wid >> 1;
                        const int e = (wid & 1) * 64 + lane * 2;
                        const float* vsel = (which == 0) ? g1sh
                                          : (which == 1) ? (Psh + cur2 * 128)
                                          : (which == 2) ? v2sh : vbssh;
                        float2 yv = *(const float2*)&ysh[e];
                        float2 vv = *(const float2*)&vsel[e];
                        float v = warpsum(fmaf(vv.x, yv.x, vv.y * yv.y));
                        if (lane == 0) dparts[wid] = v;
                    }
                }
                __syncthreads();   // S2

                if (tid < 128) {
                    const float g1y  = dparts[0] + dparts[1];
                    const float Pty  = dparts[2] + dparts[3];
                    const float v2y  = dparts[4] + dparts[5];
                    const float vbsy = dparts[6] + dparts[7];
                    float su2 = (wsumA[0] + wsumA[1]) + (wsumA[2] + wsumA[3])
                              + (wsumA[4] + wsumA[5]) + (wsumA[6] + wsumA[7]);
                    float q2 = (wsumB[0] + wsumB[1]) + (wsumB[2] + wsumB[3])
                             + (wsumB[4] + wsumB[5]) + (wsumB[6] + wsumB[7]);
                    const float SXt = sxs[cur2];

                    const float mu = g1y * invD;
                    const float var = su2 * invD - mu * mu;
                    const float rr = rsqrtf(var + kEPS);
                    const float r2 = rr * rr;
                    const float mdn  = (cc * invD) * (rr * (v2y - mu * S2v) + SBSv - SXt);
                    const float mdnn = (cc * invD) * (r2 * (q2 - 2.f * mu * v2y + mu * mu * S2v)
                                                      + rr * (vbsy - mu * SBSv)
                                                      - rr * (Pty - mu * SXt));
                    const float a1 = cc * r2;
                    const float a2 = -r2 * mdnn;
                    const float a3 = -cc * rr;
                    const float a4 = -cc * r2 * mu;
                    const float a5 = cc * rr;
                    const float a6 = rr * (mdnn * rr * mu - mdn);
                    const int i = tid;
                    float dyv = a1 * G2ysh[i] + a2 * Gysh[i] + a3 * Psh[cur2 * 128 + i]
                              + a4 * v2sh[i] + a5 * vbssh[i] + a6 * g1sh[i];
                    dysh[i] = dyv;
                    d_DY[seqbase + t * kHD + i] = dyv;
                }
                if ((t & 127) == 127) __threadfence();
                __syncthreads();   // S3
                if ((t & 127) == 127 && tid == 0)
                    atomicExch(&d_prog[bid], (t >> 7) + 1);

                int tmp = prevb; prevb = curb; curb = nextb; nextb = tmp;
            }
        }
    } else {
        // ================= CONSUMER =================
        float* Wsh = sm;                      // 128 x PITCH  (W_c, row-major [d][n])
        float* Msh = Wsh + 128 * PITCH;       // 128 x PITCH  (tril(S) transposed)
        float* As  = Msh + 128 * PITCH;       // 16 x GP
        float* Bs  = As + 16 * GP;            // 16 x GP
        const int kb = bid - kNH * kB;
        const int k = kb >> 1;
        const int bq = kb & 1;
        const int tx = tid & 15, ty = tid >> 4;
        const int m = tid >> 2, kq = tid & 3;

        for (int idx = tid; idx < kHD * kHD; idx += 256)
            Wsh[(idx >> 7) * PITCH + (idx & 127)] = W0[(size_t)k * kHD * kHD + idx];
        __syncthreads();

        for (int c = 0; c < kNC; c++) {
            const int base = k * kBT + bq * kT + c * kC;

            if (tid == 0) {
                while (*(volatile int*)&d_prog[kb] < c + 1) __nanosleep(256);
            }
            __syncthreads();
            __threadfence();

            float acc[8][8];
            #pragma unroll
            for (int r = 0; r < 8; r++)
                #pragma unroll
                for (int q = 0; q < 8; q++) acc[r][q] = 0.f;

            // ---- Phase 1: S = Zpsi_c @ Z_c^T -> Msh (tril, transposed) ----
            for (int d0 = 0; d0 < kHD; d0 += 16) {
                #pragma unroll
                for (int h2 = 0; h2 < 2; h2++) {
                    int mm = m + h2 * 64;
                    float4 va = *(const float4*)&d_ZPSI[(size_t)(base + mm) * kHD + d0 + kq * 4];
                    As[(kq * 4 + 0) * GP + mm] = va.x;
                    As[(kq * 4 + 1) * GP + mm] = va.y;
                    As[(kq * 4 + 2) * GP + mm] = va.z;
                    As[(kq * 4 + 3) * GP + mm] = va.w;
                    float4 vb = *(const float4*)&d_Z[(size_t)(base + mm) * kHD + d0 + kq * 4];
                    Bs[(kq * 4 + 0) * GP + mm] = vb.x;
                    Bs[(kq * 4 + 1) * GP + mm] = vb.y;
                    Bs[(kq * 4 + 2) * GP + mm] = vb.z;
                    Bs[(kq * 4 + 3) * GP + mm] = vb.w;
                }
                __syncthreads();
                #pragma unroll
                for (int kk = 0; kk < 16; kk++) {
                    float a[8], bb[8];
                    *(float4*)&a[0]  = *(const float4*)&As[kk * GP + ty * 8];
                    *(float4*)&a[4]  = *(const float4*)&As[kk * GP + ty * 8 + 4];
                    *(float4*)&bb[0] = *(const float4*)&Bs[kk * GP + tx * 8];
                    *(float4*)&bb[4] = *(const float4*)&Bs[kk * GP + tx * 8 + 4];
                    #pragma unroll
                    for (int r = 0; r < 8; r++)
                        #pragma unroll
                        for (int q = 0; q < 8; q++) acc[r][q] = fmaf(a[r], bb[q], acc[r][q]);
                }
                __syncthreads();
            }
            #pragma unroll
            for (int r = 0; r < 8; r++) {
                int t = ty * 8 + r;
                #pragma unroll
                for (int q = 0; q < 8; q++) {
                    int rr = tx * 8 + q;
                    Msh[rr * PITCH + t] = (rr <= t) ? acc[r][q] : 0.f;
                }
            }
            #pragma unroll
            for (int r = 0; r < 8; r++)
                #pragma unroll
                for (int q = 0; q < 8; q++) acc[r][q] = 0.f;
            __syncthreads();

            // ---- Phase 2: acc = Zpsi_c @ Wsh (W read directly from smem) ----
            for (int d0 = 0; d0 < kHD; d0 += 16) {
                #pragma unroll
                for (int h2 = 0; h2 < 2; h2++) {
                    int mm = m + h2 * 64;
                    float4 va = *(const float4*)&d_ZPSI[(size_t)(base + mm) * kHD + d0 + kq * 4];
                    As[(kq * 4 + 0) * GP + mm] = va.x;
                    As[(kq * 4 + 1) * GP + mm] = va.y;
                    As[(kq * 4 + 2) * GP + mm] = va.z;
                    As[(kq * 4 + 3) * GP + mm] = va.w;
                }
                __syncthreads();
                #pragma unroll
                for (int kk = 0; kk < 16; kk++) {
                    float a[8], bb[8];
                    *(float4*)&a[0]  = *(const float4*)&As[kk * GP + ty * 8];
                    *(float4*)&a[4]  = *(const float4*)&As[kk * GP + ty * 8 + 4];
                    *(float4*)&bb[0] = *(const float4*)&Wsh[(d0 + kk) * PITCH + tx * 8];
                    *(float4*)&bb[4] = *(const float4*)&Wsh[(d0 + kk) * PITCH + tx * 8 + 4];
                    #pragma unroll
                    for (int r = 0; r < 8; r++)
                        #pragma unroll
                        for (int q = 0; q < 8; q++) acc[r][q] = fmaf(a[r], bb[q], acc[r][q]);
                }
                __syncthreads();
            }

            // ---- Phase 3: acc -= tril(S) @ DY_c ----
            for (int r0 = 0; r0 < kC; r0 += 16) {
                int f = tid;
                #pragma unroll
                for (int it = 0; it < 2; it++, f += 256) {
                    int kk = f >> 5, c4 = f & 31;
                    *(float4*)&Bs[kk * GP + c4 * 4] =
                        *(const float4*)&d_DY[(size_t)(base + r0 + kk) * kHD + c4 * 4];
                }
                __syncthreads();
                #pragma unroll
                for (int kk = 0; kk < 16; kk++) {
                    float a[8], bb[8];
                    *(float4*)&a[0]  = *(const float4*)&Msh[(r0 + kk) * PITCH + ty * 8];
                    *(float4*)&a[4]  = *(const float4*)&Msh[(r0 + kk) * PITCH + ty * 8 + 4];
                    *(float4*)&bb[0] = *(const float4*)&Bs[kk * GP + tx * 8];
                    *(float4*)&bb[4] = *(const float4*)&Bs[kk * GP + tx * 8 + 4];
                    #pragma unroll
                    for (int r = 0; r < 8; r++)
                        #pragma unroll
                        for (int q = 0; q < 8; q++) acc[r][q] = fmaf(-a[r], bb[q], acc[r][q]);
                }
                __syncthreads();
            }

            // store Q_c
            #pragma unroll
            for (int r = 0; r < 8; r++) {
                int t = base + ty * 8 + r;
                *(float4*)&d_Q[(size_t)t * kHD + tx * 8]     = make_float4(acc[r][0], acc[r][1], acc[r][2], acc[r][3]);
                *(float4*)&d_Q[(size_t)t * kHD + tx * 8 + 4] = make_float4(acc[r][4], acc[r][5], acc[r][6], acc[r][7]);
            }

            // ---- Phase 4: W_{c+1} = W_c - Z_c^T @ DY_c ----
            if (c < kNC - 1) {
                #pragma unroll
                for (int r = 0; r < 8; r++)
                    #pragma unroll
                    for (int q = 0; q < 8; q++) acc[r][q] = 0.f;
                for (int r0 = 0; r0 < kC; r0 += 16) {
                    int f = tid;
                    #pragma unroll
                    for (int it = 0; it < 2; it++, f += 256) {
                        int kk = f >> 5, c4 = f & 31;
                        *(float4*)&As[kk * GP + c4 * 4] =
                            *(const float4*)&d_Z[(size_t)(base + r0 + kk) * kHD + c4 * 4];
                        *(float4*)&Bs[kk * GP + c4 * 4] =
                            *(const float4*)&d_DY[(size_t)(base + r0 + kk) * kHD + c4 * 4];
                    }
                    __syncthreads();
                    #pragma unroll
                    for (int kk = 0; kk < 16; kk++) {
                        float a[8], bb[8];
                        *(float4*)&a[0]  = *(const float4*)&As[kk * GP + ty * 8];
                        *(float4*)&a[4]  = *(const float4*)&As[kk * GP + ty * 8 + 4];
                        *(float4*)&bb[0] = *(const float4*)&Bs[kk * GP + tx * 8];
                        *(float4*)&bb[4] = *(const float4*)&Bs[kk * GP + tx * 8 + 4];
                        #pragma unroll
                        for (int r = 0; r < 8; r++)
                            #pragma unroll
                            for (int q = 0; q < 8; q++) acc[r][q] = fmaf(a[r], bb[q], acc[r][q]);
                    }
                    __syncthreads();
                }
                #pragma unroll
                for (int r = 0; r < 8; r++)
                    #pragma unroll
                    for (int q = 0; q < 8; q++)
                        Wsh[(ty * 8 + r) * PITCH + tx * 8 + q] -= acc[r][q];
                __syncthreads();
            }
        }
    }
}

// ---------------- output GEMM ----------------
__global__ void __launch_bounds__(256) gemm_out_kernel(const float* __restrict__ h,
                                                       float* __restrict__ out) {
    const int n0 = blockIdx.x * 128;
    const int m0 = blockIdx.y * 128;
    __shared__ float As[16 * GP];
    __shared__ float Bs[16 * GP];
    const int tid = threadIdx.x;
    const int tx = tid & 15, ty = tid >> 4;
    ull acc2[8][4];
    #pragma unroll
    for (int r = 0; r < 8; r++)
        #pragma unroll
        for (int c = 0; c < 4; c++) acc2[r][c] = 0ULL;

    for (int k0 = 0; k0 < kNH * kHD; k0 += 16) {
        const int head = k0 >> 7;
        const int j0 = k0 & 127;
        const float* Aq = d_Q + (size_t)head * kBT * kHD;
        {
            int m = tid >> 2, kq = tid & 3;
            #pragma unroll
            for (int h2 = 0; h2 < 2; h2++) {
                int mm = m + h2 * 64;
                float4 v = *(const float4*)&Aq[(size_t)(m0 + mm) * kHD + j0 + kq * 4];
                As[(kq * 4 + 0) * GP + mm] = v.x;
                As[(kq * 4 + 1) * GP + mm] = v.y;
                As[(kq * 4 + 2) * GP + mm] = v.z;
                As[(kq * 4 + 3) * GP + mm] = v.w;
            }
        }
        {
            int f = tid;
            #pragma unroll
            for (int it = 0; it < 2; it++, f += 256) {
                int kk = f >> 5, n4 = f & 31;
                float4 v = *(const float4*)&h[(size_t)(k0 + kk) * kD + n0 + n4 * 4];
                *(float4*)&Bs[kk * GP + n4 * 4] = v;
            }
        }
        __syncthreads();
        #pragma unroll
        for (int kk = 0; kk < 16; kk++) {
            float a[8];
            *(float4*)&a[0]  = *(const float4*)&As[kk * GP + ty * 8];
            *(float4*)&a[4]  = *(const float4*)&As[kk * GP + ty * 8 + 4];
            ulonglong2 b0 = *(const ulonglong2*)&Bs[kk * GP + tx * 8];
            ulonglong2 b1 = *(const ulonglong2*)&Bs[kk * GP + tx * 8 + 4];
            #pragma unroll
            for (int r = 0; r < 8; r++) {
                ull a2 = pack2(a[r], a[r]);
                acc2[r][0] = fma2(a2, b0.x, acc2[r][0]);
                acc2[r][1] = fma2(a2, b0.y, acc2[r][1]);
                acc2[r][2] = fma2(a2, b1.x, acc2[r][2]);
                acc2[r][3] = fma2(a2, b1.y, acc2[r][3]);
            }
        }
        __syncthreads();
    }
    #pragma unroll
    for (int r = 0; r < 8; r++) {
        int mm = m0 + ty * 8 + r;
        *(ulonglong2*)&out[(size_t)mm * kD + n0 + tx * 8]     = make_ulonglong2(acc2[r][0], acc2[r][1]);
        *(ulonglong2*)&out[(size_t)mm * kD + n0 + tx * 8 + 4] = make_ulonglong2(acc2[r][2], acc2[r][3]);
    }
}

// ---------------- launch ----------------
extern "C" void kernel_launch(void* const* d_in, const int* in_sizes, int n_in,
                              void* d_out, int out_size) {
    const float* X   = (const float*)d_in[0];
    const float* psi = (const float*)d_in[1];
    const float* phi = (const float*)d_in[2];
    const float* W0  = (const float*)d_in[3];
    const float* g   = (const float*)d_in[4];
    const float* h   = (const float*)d_in[5];
    const float* lns = (const float*)d_in[6];
    const float* lnb = (const float*)d_in[7];
    float* out = (float*)d_out;
    (void)in_sizes; (void)n_in; (void)out_size;

    float* gptr = nullptr;
    cudaGetSymbolAddress((void**)&gptr, d_G);

    cudaFuncSetAttribute(fused_kernel, cudaFuncAttributeMaxDynamicSharedMemorySize, FUSED_SMEM_BYTES);

    prep_kernel<<<dim3(kNH, 9), 256>>>(g, lns, lnb);
    sx_kernel<<<kBT, 192>>>(X, lns);
    gemm_proj_kernel<<<dim3(1, kBT / 128, 3 * kNH), 256>>>(X, phi, psi, g, lns);
    fused_kernel<<<2 * kNH * kB, 256, FUSED_SMEM_BYTES>>>(W0, gptr);
    gemm_out_kernel<<<dim3(kD / 128, kBT / 128), 256>>>(h, out);
}

// round 17
// speedup vs baseline: 2.5212x; 1.0505x over previous
#include <cuda_runtime.h>
#include <cuda_bf16.h>

// ---------------- problem constants ----------------
constexpr int kNH = 6;
constexpr int kD  = 768;
constexpr int kHD = 128;
constexpr int kB  = 2;
constexpr int kT  = 2048;
constexpr int kBT = kB * kT;          // 4096
constexpr int kC  = 128;              // chunk size
constexpr int kNC = kT / kC;          // 16 chunks per sequence
constexpr int kNBLK = kBT / 128;      // 32 token blocks
constexpr int kProjItems = 3 * kNH * kNBLK;  // 576
constexpr int kOutTiles  = kNBLK * (kD / 128); // 192
constexpr int kNPROD = 120;
constexpr float kEPS = 1e-6f;

constexpr int PITCH = 132;
constexpr int GP    = 132;

typedef unsigned long long ull;

// ---------------- device scratch ----------------
__device__ float d_Z    [kNH * kBT * kHD];
__device__ float d_ZPSI [kNH * kBT * kHD];
__device__ float d_P    [kNH * kBT * kHD];
__device__ float d_DY   [kNH * kBT * kHD];
__device__ float d_Q    [kNH * kBT * kHD];
__device__ float d_SX   [kNH * kBT];
__device__ float d_G    [kNH * kHD * kHD];
__device__ float d_G2   [kNH * kHD * kHD];
__device__ float d_g1   [kNH * kHD];
__device__ float d_v2   [kNH * kHD];
__device__ float d_vbs  [kNH * kHD];
__device__ float d_S2   [kNH];
__device__ float d_SBS  [kNH];
__device__ int   d_flagH[kNH];
__device__ int   d_prog [kNH * kB];     // scan chunk progress
__device__ int   d_projcnt[kNBLK];      // proj blocks done per token block (18 = ready)
__device__ int   d_qcnt[kNBLK];         // Q chunks done per token block (6 = ready)
__device__ int   d_ticket[1];           // out-tile ticket

// ---------------- f32x2 helpers ----------------
__device__ __forceinline__ ull fma2(ull a, ull b, ull c) {
    ull d;
    asm("fma.rn.f32x2 %0, %1, %2, %3;" : "=l"(d) : "l"(a), "l"(b), "l"(c));
    return d;
}
__device__ __forceinline__ ull pack2(float lo, float hi) {
    ull r;
    asm("mov.b64 %0, {%1, %2};" : "=l"(r) : "f"(lo), "f"(hi));
    return r;
}
__device__ __forceinline__ float hsum2(ull v) {
    float lo, hi;
    asm("mov.b64 {%0, %1}, %2;" : "=f"(lo), "=f"(hi) : "l"(v));
    return lo + hi;
}
__device__ __forceinline__ float warpsum(float v) {
    #pragma unroll
    for (int o = 16; o > 0; o >>= 1) v += __shfl_xor_sync(0xFFFFFFFFu, v, o);
    return v;
}

// ---------------- prep: G/G2 slices (y<8), rowstats+flag+counter-reset (y==8) ----------------
__global__ void __launch_bounds__(256) prep_kernel(const float* __restrict__ g,
                                                   const float* __restrict__ s,
                                                   const float* __restrict__ b) {
    const int k = blockIdx.x;
    const int y = blockIdx.y;
    const int tid = threadIdx.x;

    if (y < 8) {
        __shared__ float gsh[128 * 33];
        __shared__ float wsh[32];
        const int mode = y >> 2;
        const int rb = (y & 3) * 32;
        const int tx = tid & 15, ty = tid >> 4;
        float acc[2][8];
        #pragma unroll
        for (int r = 0; r < 2; r++)
            #pragma unroll
            for (int c = 0; c < 8; c++) acc[r][c] = 0.f;

        for (int d0 = 0; d0 < kD; d0 += 32) {
            for (int f = tid; f < 128 * 32; f += 256) {
                int i = f >> 5, dd = f & 31;
                gsh[i * 33 + dd] = g[(size_t)(k * kHD + i) * kD + d0 + dd];
            }
            if (tid < 32) {
                float sv = s[k * kD + d0 + tid];
                wsh[tid] = mode ? sv * sv : 1.0f;
            }
            __syncthreads();
            #pragma unroll 4
            for (int dd = 0; dd < 32; dd++) {
                float wv = wsh[dd];
                float a0 = gsh[(rb + ty * 2 + 0) * 33 + dd] * wv;
                float a1 = gsh[(rb + ty * 2 + 1) * 33 + dd] * wv;
                float bb[8];
                #pragma unroll
                for (int c = 0; c < 8; c++) bb[c] = gsh[(tx * 8 + c) * 33 + dd];
                #pragma unroll
                for (int c = 0; c < 8; c++) {
                    acc[0][c] = fmaf(a0, bb[c], acc[0][c]);
                    acc[1][c] = fmaf(a1, bb[c], acc[1][c]);
                }
            }
            __syncthreads();
        }
        float* dst = (mode ? d_G2 : d_G) + k * kHD * kHD;
        #pragma unroll
        for (int r = 0; r < 2; r++)
            #pragma unroll
            for (int c = 0; c < 8; c++)
                dst[(rb + ty * 2 + r) * kHD + tx * 8 + c] = acc[r][c];
    } else {
        if (tid < 2) d_prog[k * 2 + tid] = 0;
        if (k == 0) {
            if (tid < kNBLK) { d_projcnt[tid] = 0; d_qcnt[tid] = 0; }
            if (tid == kNBLK) d_ticket[0] = 0;
        }
        if (tid < 128) {
            float a1 = 0.f, a2 = 0.f, a3 = 0.f;
            const float* grow = g + (size_t)(k * kHD + tid) * kD;
            const float* srow = s + k * kD;
            const float* brow = b + k * kD;
            for (int d = 0; d < kD; d++) {
                float gv = grow[d], sv = srow[d], bv = brow[d];
                a1 += gv;
                a2 = fmaf(gv, sv * sv, a2);
                a3 = fmaf(gv, bv * sv, a3);
            }
            d_g1[k * kHD + tid]  = a1;
            d_v2[k * kHD + tid]  = a2;
            d_vbs[k * kHD + tid] = a3;
        }
        float s2p = 0.f, sbp = 0.f;
        int ok = 1;
        for (int d = tid; d < kD; d += 256) {
            float sv = s[k * kD + d], bv = b[k * kD + d];
            s2p = fmaf(sv, sv, s2p);
            sbp = fmaf(bv, sv, sbp);
            ok &= (sv == 1.0f) && (bv == 0.0f);
        }
        __shared__ float red[512];
        __shared__ int oksh;
        if (tid == 0) oksh = 1;
        red[tid] = s2p; red[256 + tid] = sbp;
        __syncthreads();
        if (!__all_sync(0xFFFFFFFFu, ok) && (tid & 31) == 0) atomicAnd(&oksh, 0);
        for (int o = 128; o > 0; o >>= 1) {
            if (tid < o) { red[tid] += red[tid + o]; red[256 + tid] += red[256 + tid + o]; }
            __syncthreads();
        }
        if (tid == 0) { d_S2[k] = red[0]; d_SBS[k] = red[256]; d_flagH[k] = oksh; }
    }
}

// ---------------- SX ----------------
__global__ void sx_kernel(const float* __restrict__ X, const float* __restrict__ s) {
    const int bt = blockIdx.x;
    const int w = threadIdx.x >> 5;
    const int lane = threadIdx.x & 31;
    float acc = 0.f;
    for (int d0 = lane * 4; d0 < kD; d0 += 128) {
        float4 xv = *(const float4*)&X[bt * kD + d0];
        float4 sv = *(const float4*)&s[w * kD + d0];
        acc = fmaf(xv.x, sv.x, acc);
        acc = fmaf(xv.y, sv.y, acc);
        acc = fmaf(xv.z, sv.z, acc);
        acc = fmaf(xv.w, sv.w, acc);
    }
    acc = warpsum(acc);
    if (lane == 0) d_SX[w * kBT + bt] = acc;
}

// ---------------- fused mega-kernel ----------------
// bid 0-11:   scan (k=bid>>1, b=bid&1), polls projcnt at chunk boundaries
// bid 12-23:  consumer (Q reconstruction), bumps qcnt
// bid 24-143: producer (proj items in chunk-major order), then out tiles
constexpr int SCAN_SMEM_FLOATS =
    128 * PITCH + 3 * 128 + 2 * 128 + 7 * 128 + 8 + 8 + 8 + 8;
constexpr int CONS_SMEM_FLOATS = 2 * 128 * PITCH + 2 * 16 * GP;
constexpr int FUSED_SMEM_FLOATS =
    (SCAN_SMEM_FLOATS > CONS_SMEM_FLOATS) ? SCAN_SMEM_FLOATS : CONS_SMEM_FLOATS;
constexpr int FUSED_SMEM_BYTES = FUSED_SMEM_FLOATS * 4;

__global__ void __launch_bounds__(256, 1) fused_kernel(
    const float* __restrict__ X,   const float* __restrict__ phi,
    const float* __restrict__ psi, const float* __restrict__ g,
    const float* __restrict__ lns, const float* __restrict__ W0,
    const float* __restrict__ Gsrc, const float* __restrict__ h,
    float* __restrict__ out)
{
    extern __shared__ float sm[];
    const int bid = blockIdx.x;
    const int tid = threadIdx.x;

    if (bid < kNH * kB) {
        // ================= SCAN =================
        float* G2sh   = sm;
        float* zsh    = G2sh + 128 * PITCH;
        float* Psh    = zsh + 384;
        float* ysh    = Psh + 256;
        float* Gysh   = ysh + 128;
        float* G2ysh  = Gysh + 128;
        float* dysh   = G2ysh + 128;
        float* g1sh   = dysh + 128;
        float* v2sh   = g1sh + 128;
        float* vbssh  = v2sh + 128;
        float* dparts = vbssh + 128;
        float* wsumA  = dparts + 8;
        float* wsumB  = wsumA + 8;
        float* sxs    = wsumB + 8;

        const int k = bid >> 1;
        const int b = bid & 1;
        const int j = tid >> 1;
        const int half = tid & 1;
        const int wid = tid >> 5;
        const int lane = tid & 31;
        const bool fast = (d_flagH[0] & d_flagH[1] & d_flagH[2] &
                           d_flagH[3] & d_flagH[4] & d_flagH[5]) != 0;

        if (!fast) {
            for (int idx = tid; idx < kHD * kHD; idx += 256)
                G2sh[(idx >> 7) * PITCH + (idx & 127)] = d_G2[k * kHD * kHD + idx];
        }
        const int tb = k * kBT + b * kT;
        const int seqbase = tb * kHD;

        // wait for chunk 0 of this batch to be projected
        if (tid == 0) {
            while (*(volatile int*)&d_projcnt[b * kNC] < 3 * kNH) __nanosleep(128);
        }
        __syncthreads();
        __threadfence();

        if (tid < 128) {
            g1sh[tid]  = d_g1[k * kHD + tid];
            v2sh[tid]  = d_v2[k * kHD + tid];
            vbssh[tid] = d_vbs[k * kHD + tid];
            dysh[tid]  = 0.f;
            zsh[2 * 128 + tid] = 0.f;
            zsh[tid]  = d_Z[seqbase + tid];
            Psh[tid]  = d_P[seqbase + tid];
            if (tid == 0) sxs[0] = d_SX[tb];
        }
        const float S2v  = d_S2[k];
        const float SBSv = d_SBS[k];

        ull W2[32], Gr[32];
        {
            const float* wsrc = W0 + (size_t)k * kHD * kHD;
            #pragma unroll
            for (int p = 0; p < 32; p++) {
                int r0 = half * 64 + 2 * p;
                W2[p] = pack2(wsrc[(size_t)r0 * kHD + j], wsrc[(size_t)(r0 + 1) * kHD + j]);
            }
            const ulonglong2* grow = (const ulonglong2*)(Gsrc + (size_t)(k * kHD + j) * kHD + half * 64);
            #pragma unroll
            for (int p = 0; p < 16; p++) {
                ulonglong2 v = grow[p];
                Gr[2 * p] = v.x; Gr[2 * p + 1] = v.y;
            }
        }
        __syncthreads();

        const float cc = (float)kNH / (float)kD;
        const float invD = 1.f / (float)kD;
        int prevb = 2, curb = 0, nextb = 1;

        if (fast) {
            for (int t = 0; t < kT; ++t) {
                // chunk-boundary poll: next prefetch crosses into chunk (t+1)>>7
                if ((t & 127) == 127 && t + 1 < kT) {
                    if (tid == 0) {
                        int m = b * kNC + ((t + 1) >> 7);
                        while (*(volatile int*)&d_projcnt[m] < 3 * kNH) __nanosleep(128);
                    }
                    __syncthreads();
                    __threadfence();
                }
                const int cur2 = t & 1;
                const int nb2 = cur2 ^ 1;
                const float dyO = dysh[j];
                const ull dyn2 = pack2(-dyO, -dyO);

                float nz = 0.f, nP = 0.f, nsx = 0.f;
                if (t + 1 < kT) {
                    int pb = seqbase + (t + 1) * kHD;
                    if (tid < 128) {
                        nz = d_Z[pb + tid];
                        nP = d_P[pb + tid];
                        if (tid == 0) nsx = d_SX[tb + t + 1];
                    }
                }

                float ypart;
                {
                    const ulonglong2* zo2 = (const ulonglong2*)(zsh + prevb * 128 + half * 64);
                    const ulonglong2* zc2 = (const ulonglong2*)(zsh + curb * 128 + half * 64);
                    ull ya0 = 0ULL, ya1 = 0ULL, ya2 = 0ULL, ya3 = 0ULL;
                    #pragma unroll
                    for (int p = 0; p < 16; p += 2) {
                        ulonglong2 a0 = zo2[p], c0 = zc2[p];
                        ulonglong2 a1 = zo2[p + 1], c1 = zc2[p + 1];
                        ull w0 = fma2(a0.x, dyn2, W2[2 * p]);
                        ull w1 = fma2(a0.y, dyn2, W2[2 * p + 1]);
                        ull w2 = fma2(a1.x, dyn2, W2[2 * p + 2]);
                        ull w3 = fma2(a1.y, dyn2, W2[2 * p + 3]);
                        W2[2 * p] = w0; W2[2 * p + 1] = w1;
                        W2[2 * p + 2] = w2; W2[2 * p + 3] = w3;
                        ya0 = fma2(c0.x, w0, ya0);
                        ya1 = fma2(c0.y, w1, ya1);
                        ya2 = fma2(c1.x, w2, ya2);
                        ya3 = fma2(c1.y, w3, ya3);
                    }
                    ypart = hsum2(ya0) + hsum2(ya1) + hsum2(ya2) + hsum2(ya3);
                    ypart += __shfl_xor_sync(0xFFFFFFFFu, ypart, 1);
                    if (half == 0) ysh[j] = ypart;
                }
                __syncthreads();   // S1

                {
                    if (t + 1 < kT && tid < 128) {
                        zsh[nextb * 128 + tid] = nz;
                        Psh[nb2 * 128 + tid] = nP;
                        if (tid == 0) sxs[nb2] = nsx;
                    }

                    const ulonglong2* y2 = (const ulonglong2*)(ysh + half * 64);
                    ull ga0 = 0ULL, ga1 = 0ULL, ga2 = 0ULL, ga3 = 0ULL;
                    #pragma unroll
                    for (int p = 0; p < 16; p += 2) {
                        ulonglong2 y0 = y2[p], y1 = y2[p + 1];
                        ga0 = fma2(Gr[2 * p], y0.x, ga0);
                        ga1 = fma2(Gr[2 * p + 1], y0.y, ga1);
                        ga2 = fma2(Gr[2 * p + 2], y1.x, ga2);
                        ga3 = fma2(Gr[2 * p + 3], y1.y, ga3);
                    }
                    float gpartH = hsum2(ga0) + hsum2(ga1) + hsum2(ga2) + hsum2(ga3);
                    float sp = warpsum(ypart * gpartH);
                    if (lane == 0) wsumA[wid] = sp;
                    float gpart = gpartH + __shfl_xor_sync(0xFFFFFFFFu, gpartH, 1);
                    if (half == 0) Gysh[j] = gpart;

                    {
                        const int i = (wid & 3) * 32 + lane;
                        const float* vsel = (wid < 4) ? g1sh : (Psh + cur2 * 128);
                        float v = warpsum(vsel[i] * ysh[i]);
                        if (lane == 0) dparts[wid] = v;
                    }
                }
                __syncthreads();   // S2

                if (tid < 128) {
                    const float g1y = (dparts[0] + dparts[1]) + (dparts[2] + dparts[3]);
                    const float Pty = (dparts[4] + dparts[5]) + (dparts[6] + dparts[7]);
                    const float su2 = ((wsumA[0] + wsumA[1]) + (wsumA[2] + wsumA[3]))
                                    + ((wsumA[4] + wsumA[5]) + (wsumA[6] + wsumA[7]));
                    const float SXt = sxs[cur2];

                    const float mu = g1y * invD;
                    const float var = su2 * invD - mu * mu;
                    const float rr = rsqrtf(var + kEPS);
                    const float r2 = rr * rr;
                    const float mdn  = -(cc * invD) * SXt;
                    const float mdnn = (cc * invD) * (r2 * (su2 - mu * g1y)
                                                      - rr * (Pty - mu * SXt));
                    const float aG  = cc * r2 - r2 * mdnn;
                    const float a3  = -cc * rr;
                    const float ag1 = -cc * r2 * mu + rr * (mdnn * rr * mu - mdn);
                    const int i = tid;
                    float dyv = aG * Gysh[i] + a3 * Psh[cur2 * 128 + i] + ag1 * g1sh[i];
                    dysh[i] = dyv;
                    d_DY[seqbase + t * kHD + i] = dyv;
                }
                if ((t & 127) == 127) __threadfence();
                __syncthreads();   // S3
                if ((t & 127) == 127 && tid == 0)
                    atomicExch(&d_prog[bid], (t >> 7) + 1);

                int tmp = prevb; prevb = curb; curb = nextb; nextb = tmp;
            }
        } else {
            for (int t = 0; t < kT; ++t) {
                if ((t & 127) == 127 && t + 1 < kT) {
                    if (tid == 0) {
                        int m = b * kNC + ((t + 1) >> 7);
                        while (*(volatile int*)&d_projcnt[m] < 3 * kNH) __nanosleep(128);
                    }
                    __syncthreads();
                    __threadfence();
                }
                const int cur2 = t & 1;
                const int nb2 = cur2 ^ 1;
                const float dyO = dysh[j];
                const ull dyn2 = pack2(-dyO, -dyO);

                float nz = 0.f, nP = 0.f, nsx = 0.f;
                if (t + 1 < kT) {
                    int pb = seqbase + (t + 1) * kHD;
                    if (tid < 128) {
                        nz = d_Z[pb + tid];
                        nP = d_P[pb + tid];
                        if (tid == 0) nsx = d_SX[tb + t + 1];
                    }
                }

                {
                    const ulonglong2* zo2 = (const ulonglong2*)(zsh + prevb * 128 + half * 64);
                    const ulonglong2* zc2 = (const ulonglong2*)(zsh + curb * 128 + half * 64);
                    ull ya0 = 0ULL, ya1 = 0ULL;
                    #pragma unroll
                    for (int p = 0; p < 16; p++) {
                        ulonglong2 a = zo2[p], zc = zc2[p];
                        ull w0 = fma2(a.x, dyn2, W2[2 * p]);
                        ull w1 = fma2(a.y, dyn2, W2[2 * p + 1]);
                        W2[2 * p] = w0; W2[2 * p + 1] = w1;
                        ya0 = fma2(zc.x, w0, ya0);
                        ya1 = fma2(zc.y, w1, ya1);
                    }
                    float ypart = hsum2(ya0) + hsum2(ya1);
                    ypart += __shfl_xor_sync(0xFFFFFFFFu, ypart, 1);
                    if (half == 0) ysh[j] = ypart;

                    if (t + 1 < kT && tid < 128) {
                        zsh[nextb * 128 + tid] = nz;
                        Psh[nb2 * 128 + tid] = nP;
                        if (tid == 0) sxs[nb2] = nsx;
                    }
                    __syncthreads();   // S1

                    const ulonglong2* y2 = (const ulonglong2*)(ysh + half * 64);
                    ull ga0 = 0ULL, ga1 = 0ULL;
                    #pragma unroll
                    for (int p = 0; p < 16; p++) {
                        ulonglong2 yv = y2[p];
                        ga0 = fma2(Gr[2 * p], yv.x, ga0);
                        ga1 = fma2(Gr[2 * p + 1], yv.y, ga1);
                    }
                    float gpart = hsum2(ga0) + hsum2(ga1);
                    gpart += __shfl_xor_sync(0xFFFFFFFFu, gpart, 1);
                    float g2part;
                    {
                        const ulonglong2* g2r = (const ulonglong2*)(G2sh + j * PITCH + half * 64);
                        ull h0 = 0ULL, h1 = 0ULL;
                        #pragma unroll
                        for (int p = 0; p < 16; p++) {
                            ulonglong2 gv = g2r[p];
                            ulonglong2 yv = y2[p];
                            h0 = fma2(gv.x, yv.x, h0);
                            h1 = fma2(gv.y, yv.y, h1);
                        }
                        g2part = hsum2(h0) + hsum2(h1);
                        g2part += __shfl_xor_sync(0xFFFFFFFFu, g2part, 1);
                    }
                    if (half == 0) { Gysh[j] = gpart; G2ysh[j] = g2part; }

                    float ypartf = ysh[j];
                    float yv0 = (half == 0) ? ypartf : 0.f;
                    float su2p = warpsum(gpart * yv0);
                    if (lane == 0) wsumA[wid] = su2p;
                    float q2p = warpsum(g2part * yv0);
                    if (lane == 0) wsumB[wid] = q2p;

                    {
                        const int which = wid >> 1;
                        const int e = (wid & 1) * 64 + lane * 2;
                        const float* vsel = (which == 0) ? g1sh
                                          : (which == 1) ? (Psh + cur2 * 128)
                                          : (which == 2) ? v2sh : vbssh;
                        float2 yv = *(const float2*)&ysh[e];
                        float2 vv = *(const float2*)&vsel[e];
                        float v = warpsum(fmaf(vv.x, yv.x, vv.y * yv.y));
                        if (lane == 0) dparts[wid] = v;
                    }
                }
                __syncthreads();   // S2

                if (tid < 128) {
                    const float g1y  = dparts[0] + dparts[1];
                    const float Pty  = dparts[2] + dparts[3];
                    const float v2y  = dparts[4] + dparts[5];
                    const float vbsy = dparts[6] + dparts[7];
                    float su2 = (wsumA[0] + wsumA[1]) + (wsumA[2] + wsumA[3])
                              + (wsumA[4] + wsumA[5]) + (wsumA[6] + wsumA[7]);
                    float q2 = (wsumB[0] + wsumB[1]) + (wsumB[2] + wsumB[3])
                             + (wsumB[4] + wsumB[5]) + (wsumB[6] + wsumB[7]);
                    const float SXt = sxs[cur2];

                    const float mu = g1y * invD;
                    const float var = su2 * invD - mu * mu;
                    const float rr = rsqrtf(var + kEPS);
                    const float r2 = rr * rr;
                    const float mdn  = (cc * invD) * (rr * (v2y - mu * S2v) + SBSv - SXt);
                    const float mdnn = (cc * invD) * (r2 * (q2 - 2.f * mu * v2y + mu * mu * S2v)
                                                      + rr * (vbsy - mu * SBSv)
                                                      - rr * (Pty - mu * SXt));
                    const float a1 = cc * r2;
                    const float a2 = -r2 * mdnn;
                    const float a3 = -cc * rr;
                    const float a4 = -cc * r2 * mu;
                    const float a5 = cc * rr;
                    const float a6 = rr * (mdnn * rr * mu - mdn);
                    const int i = tid;
                    float dyv = a1 * G2ysh[i] + a2 * Gysh[i] + a3 * Psh[cur2 * 128 + i]
                              + a4 * v2sh[i] + a5 * vbssh[i] + a6 * g1sh[i];
                    dysh[i] = dyv;
                    d_DY[seqbase + t * kHD + i] = dyv;
                }
                if ((t & 127) == 127) __threadfence();
                __syncthreads();   // S3
                if ((t & 127) == 127 && tid == 0)
                    atomicExch(&d_prog[bid], (t >> 7) + 1);

                int tmp = prevb; prevb = curb; curb = nextb; nextb = tmp;
            }
        }
    } else if (bid < 2 * kNH * kB) {
        // ================= CONSUMER =================
        float* Wsh = sm;
        float* Msh = Wsh + 128 * PITCH;
        float* As  = Msh + 128 * PITCH;
        float* Bs  = As + 16 * GP;
        const int kb = bid - kNH * kB;
        const int k = kb >> 1;
        const int bq = kb & 1;
        const int tx = tid & 15, ty = tid >> 4;
        const int m = tid >> 2, kq = tid & 3;

        for (int idx = tid; idx < kHD * kHD; idx += 256)
            Wsh[(idx >> 7) * PITCH + (idx & 127)] = W0[(size_t)k * kHD * kHD + idx];
        __syncthreads();

        for (int c = 0; c < kNC; c++) {
            const int base = k * kBT + bq * kT + c * kC;
            const int mblk = bq * kNC + c;

            if (tid == 0) {
                while (*(volatile int*)&d_projcnt[mblk] < 3 * kNH) __nanosleep(256);
                while (*(volatile int*)&d_prog[kb] < c + 1) __nanosleep(256);
            }
            __syncthreads();
            __threadfence();

            float acc[8][8];
            #pragma unroll
            for (int r = 0; r < 8; r++)
                #pragma unroll
                for (int q = 0; q < 8; q++) acc[r][q] = 0.f;

            // Phase 1: S = Zpsi_c @ Z_c^T
            for (int d0 = 0; d0 < kHD; d0 += 16) {
                #pragma unroll
                for (int h2 = 0; h2 < 2; h2++) {
                    int mm = m + h2 * 64;
                    float4 va = *(const float4*)&d_ZPSI[(size_t)(base + mm) * kHD + d0 + kq * 4];
                    As[(kq * 4 + 0) * GP + mm] = va.x;
                    As[(kq * 4 + 1) * GP + mm] = va.y;
                    As[(kq * 4 + 2) * GP + mm] = va.z;
                    As[(kq * 4 + 3) * GP + mm] = va.w;
                    float4 vb = *(const float4*)&d_Z[(size_t)(base + mm) * kHD + d0 + kq * 4];
                    Bs[(kq * 4 + 0) * GP + mm] = vb.x;
                    Bs[(kq * 4 + 1) * GP + mm] = vb.y;
                    Bs[(kq * 4 + 2) * GP + mm] = vb.z;
                    Bs[(kq * 4 + 3) * GP + mm] = vb.w;
                }
                __syncthreads();
                #pragma unroll
                for (int kk = 0; kk < 16; kk++) {
                    float a[8], bb[8];
                    *(float4*)&a[0]  = *(const float4*)&As[kk * GP + ty * 8];
                    *(float4*)&a[4]  = *(const float4*)&As[kk * GP + ty * 8 + 4];
                    *(float4*)&bb[0] = *(const float4*)&Bs[kk * GP + tx * 8];
                    *(float4*)&bb[4] = *(const float4*)&Bs[kk * GP + tx * 8 + 4];
                    #pragma unroll
                    for (int r = 0; r < 8; r++)
                        #pragma unroll
                        for (int q = 0; q < 8; q++) acc[r][q] = fmaf(a[r], bb[q], acc[r][q]);
                }
                __syncthreads();
            }
            #pragma unroll
            for (int r = 0; r < 8; r++) {
                int t = ty * 8 + r;
                #pragma unroll
                for (int q = 0; q < 8; q++) {
                    int rr = tx * 8 + q;
                    Msh[rr * PITCH + t] = (rr <= t) ? acc[r][q] : 0.f;
                }
            }
            #pragma unroll
            for (int r = 0; r < 8; r++)
                #pragma unroll
                for (int q = 0; q < 8; q++) acc[r][q] = 0.f;
            __syncthreads();

            // Phase 2: acc = Zpsi_c @ Wsh
            for (int d0 = 0; d0 < kHD; d0 += 16) {
                #pragma unroll
                for (int h2 = 0; h2 < 2; h2++) {
                    int mm = m + h2 * 64;
                    float4 va = *(const float4*)&d_ZPSI[(size_t)(base + mm) * kHD + d0 + kq * 4];
                    As[(kq * 4 + 0) * GP + mm] = va.x;
                    As[(kq * 4 + 1) * GP + mm] = va.y;
                    As[(kq * 4 + 2) * GP + mm] = va.z;
                    As[(kq * 4 + 3) * GP + mm] = va.w;
                }
                __syncthreads();
                #pragma unroll
                for (int kk = 0; kk < 16; kk++) {
                    float a[8], bb[8];
                    *(float4*)&a[0]  = *(const float4*)&As[kk * GP + ty * 8];
                    *(float4*)&a[4]  = *(const float4*)&As[kk * GP + ty * 8 + 4];
                    *(float4*)&bb[0] = *(const float4*)&Wsh[(d0 + kk) * PITCH + tx * 8];
                    *(float4*)&bb[4] = *(const float4*)&Wsh[(d0 + kk) * PITCH + tx * 8 + 4];
                    #pragma unroll
                    for (int r = 0; r < 8; r++)
                        #pragma unroll
                        for (int q = 0; q < 8; q++) acc[r][q] = fmaf(a[r], bb[q], acc[r][q]);
                }
                __syncthreads();
            }

            // Phase 3: acc -= tril(S) @ DY_c
            for (int r0 = 0; r0 < kC; r0 += 16) {
                int f = tid;
                #pragma unroll
                for (int it = 0; it < 2; it++, f += 256) {
                    int kk = f >> 5, c4 = f & 31;
                    *(float4*)&Bs[kk * GP + c4 * 4] =
                        *(const float4*)&d_DY[(size_t)(base + r0 + kk) * kHD + c4 * 4];
                }
                __syncthreads();
                #pragma unroll
                for (int kk = 0; kk < 16; kk++) {
                    float a[8], bb[8];
                    *(float4*)&a[0]  = *(const float4*)&Msh[(r0 + kk) * PITCH + ty * 8];
                    *(float4*)&a[4]  = *(const float4*)&Msh[(r0 + kk) * PITCH + ty * 8 + 4];
                    *(float4*)&bb[0] = *(const float4*)&Bs[kk * GP + tx * 8];
                    *(float4*)&bb[4] = *(const float4*)&Bs[kk * GP + tx * 8 + 4];
                    #pragma unroll
                    for (int r = 0; r < 8; r++)
                        #pragma unroll
                        for (int q = 0; q < 8; q++) acc[r][q] = fmaf(-a[r], bb[q], acc[r][q]);
                }
                __syncthreads();
            }

            #pragma unroll
            for (int r = 0; r < 8; r++) {
                int t = base + ty * 8 + r;
                *(float4*)&d_Q[(size_t)t * kHD + tx * 8]     = make_float4(acc[r][0], acc[r][1], acc[r][2], acc[r][3]);
                *(float4*)&d_Q[(size_t)t * kHD + tx * 8 + 4] = make_float4(acc[r][4], acc[r][5], acc[r][6], acc[r][7]);
            }
            __threadfence();
            __syncthreads();
            if (tid == 0) atomicAdd(&d_qcnt[mblk], 1);

            // Phase 4: W_{c+1} = W_c - Z_c^T @ DY_c
            if (c < kNC - 1) {
                #pragma unroll
                for (int r = 0; r < 8; r++)
                    #pragma unroll
                    for (int q = 0; q < 8; q++) acc[r][q] = 0.f;
                for (int r0 = 0; r0 < kC; r0 += 16) {
                    int f = tid;
                    #pragma unroll
                    for (int it = 0; it < 2; it++, f += 256) {
                        int kk = f >> 5, c4 = f & 31;
                        *(float4*)&As[kk * GP + c4 * 4] =
                            *(const float4*)&d_Z[(size_t)(base + r0 + kk) * kHD + c4 * 4];
                        *(float4*)&Bs[kk * GP + c4 * 4] =
                            *(const float4*)&d_DY[(size_t)(base + r0 + kk) * kHD + c4 * 4];
                    }
                    __syncthreads();
                    #pragma unroll
                    for (int kk = 0; kk < 16; kk++) {
                        float a[8], bb[8];
                        *(float4*)&a[0]  = *(const float4*)&As[kk * GP + ty * 8];
                        *(float4*)&a[4]  = *(const float4*)&As[kk * GP + ty * 8 + 4];
                        *(float4*)&bb[0] = *(const float4*)&Bs[kk * GP + tx * 8];
                        *(float4*)&bb[4] = *(const float4*)&Bs[kk * GP + tx * 8 + 4];
                        #pragma unroll
                        for (int r = 0; r < 8; r++)
                            #pragma unroll
                            for (int q = 0; q < 8; q++) acc[r][q] = fmaf(a[r], bb[q], acc[r][q]);
                    }
                    __syncthreads();
                }
                #pragma unroll
                for (int r = 0; r < 8; r++)
                    #pragma unroll
                    for (int q = 0; q < 8; q++)
                        Wsh[(ty * 8 + r) * PITCH + tx * 8 + q] -= acc[r][q];
                __syncthreads();
            }
        }
    } else {
        // ================= PRODUCER (proj items, then out tiles) =================
        float* As = sm;
        float* Bs = As + 16 * GP;
        __shared__ int sidx;
        const int pid = bid - 2 * kNH * kB;    // 0..kNPROD-1
        const int tx = tid & 15, ty = tid >> 4;

        // ---- phase 1: projection items, chunk-major across batches ----
        for (int i = pid; i < kProjItems; i += kNPROD) {
            const int mi = i / 18;
            const int mblk = (mi & 1) ? (kNC + (mi >> 1)) : (mi >> 1);  // interleave b0/b1
            const int sub = i % 18;
            const int which = sub % 3;
            const int head  = sub / 3;
            const int m0 = mblk * 128;

            ull acc2[8][4];
            #pragma unroll
            for (int r = 0; r < 8; r++)
                #pragma unroll
                for (int c = 0; c < 4; c++) acc2[r][c] = 0ULL;

            const float* Bsrc = (which == 0) ? phi : psi;

            for (int k0 = 0; k0 < kD; k0 += 16) {
                {
                    int mm0 = tid >> 2, kq = tid & 3;
                    #pragma unroll
                    for (int h2 = 0; h2 < 2; h2++) {
                        int mm = mm0 + h2 * 64;
                        float4 v = *(const float4*)&X[(size_t)(m0 + mm) * kD + k0 + kq * 4];
                        As[(kq * 4 + 0) * GP + mm] = v.x;
                        As[(kq * 4 + 1) * GP + mm] = v.y;
                        As[(kq * 4 + 2) * GP + mm] = v.z;
                        As[(kq * 4 + 3) * GP + mm] = v.w;
                    }
                }
                if (which < 2) {
                    int f = tid;
                    #pragma unroll
                    for (int it = 0; it < 2; it++, f += 256) {
                        int kk = f >> 5, n4 = f & 31;
                        float4 v = *(const float4*)&Bsrc[(size_t)(head * kD + k0 + kk) * kHD + n4 * 4];
                        *(float4*)&Bs[kk * GP + n4 * 4] = v;
                    }
                } else {
                    int f = tid;
                    #pragma unroll
                    for (int it = 0; it < 2; it++, f += 256) {
                        int jj = f >> 2, kq = f & 3;
                        float4 gv = *(const float4*)&g[(size_t)(head * kHD + jj) * kD + k0 + kq * 4];
                        float4 sv = *(const float4*)&lns[head * kD + k0 + kq * 4];
                        Bs[(kq * 4 + 0) * GP + jj] = gv.x * sv.x;
                        Bs[(kq * 4 + 1) * GP + jj] = gv.y * sv.y;
                        Bs[(kq * 4 + 2) * GP + jj] = gv.z * sv.z;
                        Bs[(kq * 4 + 3) * GP + jj] = gv.w * sv.w;
                    }
                }
                __syncthreads();
                #pragma unroll
                for (int kk = 0; kk < 16; kk++) {
                    float a[8];
                    *(float4*)&a[0]  = *(const float4*)&As[kk * GP + ty * 8];
                    *(float4*)&a[4]  = *(const float4*)&As[kk * GP + ty * 8 + 4];
                    ulonglong2 b0 = *(const ulonglong2*)&Bs[kk * GP + tx * 8];
                    ulonglong2 b1 = *(const ulonglong2*)&Bs[kk * GP + tx * 8 + 4];
                    #pragma unroll
                    for (int r = 0; r < 8; r++) {
                        ull a2 = pack2(a[r], a[r]);
                        acc2[r][0] = fma2(a2, b0.x, acc2[r][0]);
                        acc2[r][1] = fma2(a2, b0.y, acc2[r][1]);
                        acc2[r][2] = fma2(a2, b1.x, acc2[r][2]);
                        acc2[r][3] = fma2(a2, b1.y, acc2[r][3]);
                    }
                }
                __syncthreads();
            }
            float* Cdst = ((which == 0) ? d_Z : (which == 1) ? d_ZPSI : d_P) + (size_t)head * kBT * kHD;
            #pragma unroll
            for (int r = 0; r < 8; r++) {
                int mm = m0 + ty * 8 + r;
                *(ulonglong2*)&Cdst[(size_t)mm * kHD + tx * 8]     = make_ulonglong2(acc2[r][0], acc2[r][1]);
                *(ulonglong2*)&Cdst[(size_t)mm * kHD + tx * 8 + 4] = make_ulonglong2(acc2[r][2], acc2[r][3]);
            }
            __threadfence();
            __syncthreads();
            if (tid == 0) atomicAdd(&d_projcnt[mblk], 1);
        }

        // ---- phase 2: output GEMM tiles (ticket-claimed, m-major) ----
        for (;;) {
            if (tid == 0) sidx = atomicAdd(&d_ticket[0], 1);
            __syncthreads();
            int idx = sidx;
            __syncthreads();
            if (idx >= kOutTiles) break;
            const int mblk = idx / (kD / 128);
            const int n0 = (idx % (kD / 128)) * 128;
            const int m0 = mblk * 128;

            if (tid == 0) {
                while (*(volatile int*)&d_qcnt[mblk] < kNH) __nanosleep(256);
            }
            __syncthreads();
            __threadfence();

            ull acc2[8][4];
            #pragma unroll
            for (int r = 0; r < 8; r++)
                #pragma unroll
                for (int c = 0; c < 4; c++) acc2[r][c] = 0ULL;

            for (int k0 = 0; k0 < kNH * kHD; k0 += 16) {
                const int head = k0 >> 7;
                const int j0 = k0 & 127;
                const float* Aq = d_Q + (size_t)head * kBT * kHD;
                {
                    int mm0 = tid >> 2, kq = tid & 3;
                    #pragma unroll
                    for (int h2 = 0; h2 < 2; h2++) {
                        int mm = mm0 + h2 * 64;
                        float4 v = *(const float4*)&Aq[(size_t)(m0 + mm) * kHD + j0 + kq * 4];
                        As[(kq * 4 + 0) * GP + mm] = v.x;
                        As[(kq * 4 + 1) * GP + mm] = v.y;
                        As[(kq * 4 + 2) * GP + mm] = v.z;
                        As[(kq * 4 + 3) * GP + mm] = v.w;
                    }
                }
                {
                    int f = tid;
                    #pragma unroll
                    for (int it = 0; it < 2; it++, f += 256) {
                        int kk = f >> 5, n4 = f & 31;
                        float4 v = *(const float4*)&h[(size_t)(k0 + kk) * kD + n0 + n4 * 4];
                        *(float4*)&Bs[kk * GP + n4 * 4] = v;
                    }
                }
                __syncthreads();
                #pragma unroll
                for (int kk = 0; kk < 16; kk++) {
                    float a[8];
                    *(float4*)&a[0]  = *(const float4*)&As[kk * GP + ty * 8];
                    *(float4*)&a[4]  = *(const float4*)&As[kk * GP + ty * 8 + 4];
                    ulonglong2 b0 = *(const ulonglong2*)&Bs[kk * GP + tx * 8];
                    ulonglong2 b1 = *(const ulonglong2*)&Bs[kk * GP + tx * 8 + 4];
                    #pragma unroll
                    for (int r = 0; r < 8; r++) {
                        ull a2 = pack2(a[r], a[r]);
                        acc2[r][0] = fma2(a2, b0.x, acc2[r][0]);
                        acc2[r][1] = fma2(a2, b0.y, acc2[r][1]);
                        acc2[r][2] = fma2(a2, b1.x, acc2[r][2]);
                        acc2[r][3] = fma2(a2, b1.y, acc2[r][3]);
                    }
                }
                __syncthreads();
            }
            #pragma unroll
            for (int r = 0; r < 8; r++) {
                int mm = m0 + ty * 8 + r;
                *(ulonglong2*)&out[(size_t)mm * kD + n0 + tx * 8]     = make_ulonglong2(acc2[r][0], acc2[r][1]);
                *(ulonglong2*)&out[(size_t)mm * kD + n0 + tx * 8 + 4] = make_ulonglong2(acc2[r][2], acc2[r][3]);
            }
        }
    }
}

// ---------------- launch ----------------
extern "C" void kernel_launch(void* const* d_in, const int* in_sizes, int n_in,
                              void* d_out, int out_size) {
    const float* X   = (const float*)d_in[0];
    const float* psi = (const float*)d_in[1];
    const float* phi = (const float*)d_in[2];
    const float* W0  = (const float*)d_in[3];
    const float* g   = (const float*)d_in[4];
    const float* h   = (const float*)d_in[5];
    const float* lns = (const float*)d_in[6];
    const float* lnb = (const float*)d_in[7];
    float* out = (float*)d_out;
    (void)in_sizes; (void)n_in; (void)out_size;

    float* gptr = nullptr;
    cudaGetSymbolAddress((void**)&gptr, d_G);

    cudaFuncSetAttribute(fused_kernel, cudaFuncAttributeMaxDynamicSharedMemorySize, FUSED_SMEM_BYTES);

    prep_kernel<<<dim3(kNH, 9), 256>>>(g, lns, lnb);
    sx_kernel<<<kBT, 192>>>(X, lns);
    fused_kernel<<<2 * kNH * kB + kNPROD, 256, FUSED_SMEM_BYTES>>>(
        X, phi, psi, g, lns, W0, gptr, h, out);
}